// round 1
// baseline (speedup 1.0000x reference)
#include <cuda_runtime.h>
#include <cstdint>

#define NN   50000
#define EE   800000
#define FIN  128
#define HIDD 64
#define C1   192          // P*HID
#define EPSB 1e-5f

// ---------------- static device scratch (no allocations allowed) ----------------
__device__ int g_is64;
__device__ __align__(256) float g_Z   [(size_t)NN * C1];
__device__ __align__(256) float g_Hpre[(size_t)NN * C1];
__device__ __align__(256) float g_Hn  [(size_t)NN * C1];
__device__ __align__(256) float g_T   [(size_t)NN * HIDD];
__device__ int   g_cnt[NN];
__device__ int   g_rowptr[NN + 1];
__device__ int   g_pos[NN];
__device__ __align__(256) int   g_col[EE];
__device__ __align__(256) float g_w  [EE];
__device__ float g_dinv[NN];
__device__ float g_sum[C1];
__device__ float g_sq [C1];
__device__ float g_scale[C1];
__device__ float g_shift[C1];

// ---------------- edge index accessor (dtype-agnostic) ----------------
__device__ __forceinline__ int edge_at(const void* p, long long i) {
    if (g_is64) return (int)((const long long*)p)[i];
    return ((const int*)p)[i];
}

// Detect whether edge_index is int64 or int32. If the data is really int32,
// the int64 view combines random index pairs -> values >= 2^32 almost surely.
__global__ void k_detect(const long long* e) {
    if (threadIdx.x == 0 && blockIdx.x == 0) {
        int ok64 = 1;
        for (int i = 0; i < 256; i++) {
            long long v = e[i];
            if (v < 0 || v >= NN) { ok64 = 0; break; }
        }
        g_is64 = ok64;
    }
}

// ---------------- graph preprocessing ----------------
__global__ void k_clear_cnt() {
    int i = blockIdx.x * blockDim.x + threadIdx.x;
    if (i < NN) g_cnt[i] = 0;
}

__global__ void k_count(const void* e) {
    int i = blockIdx.x * blockDim.x + threadIdx.x;
    if (i < EE) {
        int d = edge_at(e, (long long)EE + i);
        atomicAdd(&g_cnt[d], 1);
    }
}

__global__ void k_scan() {
    __shared__ int sh[1024];
    __shared__ int carry;
    int t = threadIdx.x;
    if (t == 0) carry = 0;
    __syncthreads();
    for (int base = 0; base < NN; base += 1024) {
        int i = base + t;
        int v = (i < NN) ? g_cnt[i] : 0;
        sh[t] = v;
        __syncthreads();
        for (int off = 1; off < 1024; off <<= 1) {
            int tv = (t >= off) ? sh[t - off] : 0;
            __syncthreads();
            sh[t] += tv;
            __syncthreads();
        }
        int excl = sh[t] - v + carry;
        if (i < NN) { g_rowptr[i] = excl; g_pos[i] = excl; }
        __syncthreads();
        if (t == 1023) carry += sh[1023];
        __syncthreads();
    }
    if (t == 0) g_rowptr[NN] = carry;
}

__global__ void k_dinv() {
    int i = blockIdx.x * blockDim.x + threadIdx.x;
    if (i < NN) g_dinv[i] = rsqrtf((float)g_cnt[i] + 1.0f);  // +1 self loop
}

__global__ void k_fill(const void* e) {
    int i = blockIdx.x * blockDim.x + threadIdx.x;
    if (i < EE) {
        int s = edge_at(e, i);
        int d = edge_at(e, (long long)EE + i);
        int p = atomicAdd(&g_pos[d], 1);
        g_col[p] = s;
        g_w[p]   = g_dinv[s] * g_dinv[d];
    }
}

// ---------------- SpMM: out[v] = dinv[v]^2 * Z[v] + sum_e w[e]*Z[col[e]], 64 cols ----
__global__ __launch_bounds__(256) void spmm64(
    const float* __restrict__ Z, int ldz,
    float* __restrict__ out, int ldo)
{
    int warp = (blockIdx.x * blockDim.x + threadIdx.x) >> 5;
    int lane = threadIdx.x & 31;
    if (warp >= NN) return;
    float dv = g_dinv[warp];
    float ws = dv * dv;
    const float2* zr = (const float2*)(Z + (size_t)warp * ldz);
    float2 zv = zr[lane];
    float ax = ws * zv.x, ay = ws * zv.y;
    int e0 = g_rowptr[warp], e1 = g_rowptr[warp + 1];
    #pragma unroll 4
    for (int e = e0; e < e1; e++) {
        int c   = __ldg(&g_col[e]);
        float wt = __ldg(&g_w[e]);
        const float2* zc = (const float2*)(Z + (size_t)c * ldz);
        float2 v = zc[lane];
        ax = fmaf(wt, v.x, ax);
        ay = fmaf(wt, v.y, ay);
    }
    float2 o; o.x = ax; o.y = ay;
    ((float2*)(out + (size_t)warp * ldo))[lane] = o;
}

// copy first 64 columns of Z (ld 192) into Hpre (ld 192)
__global__ void k_copy64(const float* __restrict__ Z, float* __restrict__ H) {
    int idx = blockIdx.x * blockDim.x + threadIdx.x;   // over NN*16 float4
    if (idx >= NN * 16) return;
    int r = idx >> 4, c4 = idx & 15;
    const float4* s = (const float4*)(Z + (size_t)r * C1) + c4;
    float4* d = (float4*)(H + (size_t)r * C1) + c4;
    *d = *s;
}

// ---------------- BatchNorm (training-mode, per-column over nodes) ----------------
__global__ void k_clear_stats() {
    int c = threadIdx.x;
    if (c < C1) { g_sum[c] = 0.f; g_sq[c] = 0.f; }
}

__global__ void bn_stats(const float* __restrict__ H) {
    int c = threadIdx.x;   // blockDim = 192
    float s = 0.f, q = 0.f;
    for (int r = blockIdx.x; r < NN; r += gridDim.x) {
        float v = H[(size_t)r * C1 + c];
        s += v;
        q = fmaf(v, v, q);
    }
    atomicAdd(&g_sum[c], s);
    atomicAdd(&g_sq[c], q);
}

__global__ void bn_final(const float* __restrict__ g, const float* __restrict__ be) {
    int c = threadIdx.x;
    if (c < C1) {
        float mu  = g_sum[c] * (1.0f / NN);
        float var = g_sq[c] * (1.0f / NN) - mu * mu;
        float inv = rsqrtf(var + EPSB);
        float sc  = inv * g[c];
        g_scale[c] = sc;
        g_shift[c] = be[c] - mu * sc;
    }
}

__global__ void bn_apply(const float* __restrict__ H, float* __restrict__ O) {
    int idx = blockIdx.x * blockDim.x + threadIdx.x;   // over NN*48 float4
    if (idx >= NN * 48) return;
    int c4 = (idx % 48) * 4;
    float4 v = *((const float4*)H + idx);
    float4 o;
    o.x = fmaxf(0.f, fmaf(v.x, g_scale[c4 + 0], g_shift[c4 + 0]));
    o.y = fmaxf(0.f, fmaf(v.y, g_scale[c4 + 1], g_shift[c4 + 1]));
    o.z = fmaxf(0.f, fmaf(v.z, g_scale[c4 + 2], g_shift[c4 + 2]));
    o.w = fmaxf(0.f, fmaf(v.w, g_scale[c4 + 3], g_shift[c4 + 3]));
    *((float4*)O + idx) = o;
}

// ---------------- fp32 tiled GEMM: C[M,NC] = A[M,K] @ Bcat, blockIdx.y = 64-col block --
#define BM 128
#define BN 64
#define BK 16

__global__ __launch_bounds__(256) void sgemm_k(
    const float* __restrict__ A, const float* __restrict__ Bmat,
    float* __restrict__ C, int M, int K, int NC,
    const float* __restrict__ bias)
{
    __shared__ float As[BK][BM + 4];
    __shared__ float Bs[BK][BN];
    int p = blockIdx.y;
    const float* Bp = Bmat + (size_t)p * K * BN;   // W[p] is [K,64] row-major
    int rowBase = blockIdx.x * BM;
    int tid = threadIdx.x;
    int tx = tid & 15;     // column group 0..15
    int ty = tid >> 4;     // row group 0..15

    float acc[8][4];
    #pragma unroll
    for (int i = 0; i < 8; i++)
        #pragma unroll
        for (int j = 0; j < 4; j++) acc[i][j] = 0.f;

    for (int k0 = 0; k0 < K; k0 += BK) {
        // load A tile: 512 float4 slots, 2 per thread
        #pragma unroll
        for (int l = 0; l < 2; l++) {
            int slot = tid + l * 256;
            int ar  = slot >> 2;
            int ac4 = slot & 3;
            int grow = rowBase + ar;
            float4 v = make_float4(0.f, 0.f, 0.f, 0.f);
            if (grow < M)
                v = *(const float4*)(A + (size_t)grow * K + k0 + ac4 * 4);
            As[ac4 * 4 + 0][ar] = v.x;
            As[ac4 * 4 + 1][ar] = v.y;
            As[ac4 * 4 + 2][ar] = v.z;
            As[ac4 * 4 + 3][ar] = v.w;
        }
        // load B tile: 256 float4 slots, 1 per thread
        {
            int br  = tid >> 4;
            int bc4 = tid & 15;
            float4 v = *(const float4*)(Bp + (size_t)(k0 + br) * BN + bc4 * 4);
            *(float4*)&Bs[br][bc4 * 4] = v;
        }
        __syncthreads();
        #pragma unroll
        for (int kk = 0; kk < BK; kk++) {
            float4 a0 = *(const float4*)&As[kk][ty * 8];
            float4 a1 = *(const float4*)&As[kk][ty * 8 + 4];
            float4 b0 = *(const float4*)&Bs[kk][tx * 4];
            float a[8] = {a0.x, a0.y, a0.z, a0.w, a1.x, a1.y, a1.z, a1.w};
            float b[4] = {b0.x, b0.y, b0.z, b0.w};
            #pragma unroll
            for (int i = 0; i < 8; i++)
                #pragma unroll
                for (int j = 0; j < 4; j++)
                    acc[i][j] = fmaf(a[i], b[j], acc[i][j]);
        }
        __syncthreads();
    }
    int colBase = p * BN + tx * 4;
    float4 bb = make_float4(0.f, 0.f, 0.f, 0.f);
    if (bias) {
        bb.x = bias[colBase + 0]; bb.y = bias[colBase + 1];
        bb.z = bias[colBase + 2]; bb.w = bias[colBase + 3];
    }
    #pragma unroll
    for (int i = 0; i < 8; i++) {
        int r = rowBase + ty * 8 + i;
        if (r < M) {
            float4 o;
            o.x = acc[i][0] + bb.x;
            o.y = acc[i][1] + bb.y;
            o.z = acc[i][2] + bb.z;
            o.w = acc[i][3] + bb.w;
            *(float4*)(C + (size_t)r * NC + colBase) = o;
        }
    }
}

// ---------------- host launch ----------------
extern "C" void kernel_launch(void* const* d_in, const int* in_sizes, int n_in,
                              void* d_out, int out_size) {
    const float* x   = (const float*)d_in[0];
    const void*  ei  = d_in[1];
    const float* W1  = (const float*)d_in[2];
    // d_in[3] = B1  (absorbed by BatchNorm — mathematically a no-op)
    const float* g1  = (const float*)d_in[4];
    const float* be1 = (const float*)d_in[5];
    const float* W2  = (const float*)d_in[6];
    // d_in[7] = B2  (absorbed by BatchNorm)
    const float* g2  = (const float*)d_in[8];
    const float* be2 = (const float*)d_in[9];
    const float* Wfc = (const float*)d_in[10];
    const float* bfc = (const float*)d_in[11];
    float* out = (float*)d_out;

    float *Z, *Hpre, *Hn, *T;
    cudaGetSymbolAddress((void**)&Z,    g_Z);
    cudaGetSymbolAddress((void**)&Hpre, g_Hpre);
    cudaGetSymbolAddress((void**)&Hn,   g_Hn);
    cudaGetSymbolAddress((void**)&T,    g_T);

    const int TB = 256;
    const int nBlkN   = (NN + TB - 1) / TB;
    const int nBlkE   = (EE + TB - 1) / TB;
    const int nBlkSp  = (NN + 7) / 8;            // warp per row, 8 warps/block
    const int nBlkCp  = (NN * 16 + TB - 1) / TB;
    const int nBlkAp  = (NN * 48 + TB - 1) / TB;
    const dim3 gemmG((NN + BM - 1) / BM, 3);
    const dim3 gemmO((NN + BM - 1) / BM, 1);

    // preprocessing: dtype sniff, degrees, CSR, norms
    k_detect<<<1, 32>>>((const long long*)ei);
    k_clear_cnt<<<nBlkN, TB>>>();
    k_count<<<nBlkE, TB>>>(ei);
    k_scan<<<1, 1024>>>();
    k_dinv<<<nBlkN, TB>>>();
    k_fill<<<nBlkE, TB>>>(ei);

    // ---- layer 1:  Z = x @ [W1_0|W1_1|W1_2]  then propagate 64-wide slices ----
    sgemm_k<<<gemmG, TB>>>(x, W1, Z, NN, FIN, C1, nullptr);
    k_copy64<<<nBlkCp, TB>>>(Z, Hpre);                       // power 0
    spmm64<<<nBlkSp, TB>>>(Z + HIDD,     C1, Hpre + HIDD,     C1);  // A z1
    spmm64<<<nBlkSp, TB>>>(Z + 2 * HIDD, C1, T,               HIDD); // A z2
    spmm64<<<nBlkSp, TB>>>(T,            HIDD, Hpre + 2 * HIDD, C1); // A^2 z2
    k_clear_stats<<<1, C1>>>();
    bn_stats<<<512, C1>>>(Hpre);
    bn_final<<<1, C1>>>(g1, be1);
    bn_apply<<<nBlkAp, TB>>>(Hpre, Hn);

    // ---- layer 2 ----
    sgemm_k<<<gemmG, TB>>>(Hn, W2, Z, NN, C1, C1, nullptr);
    k_copy64<<<nBlkCp, TB>>>(Z, Hpre);
    spmm64<<<nBlkSp, TB>>>(Z + HIDD,     C1, Hpre + HIDD,     C1);
    spmm64<<<nBlkSp, TB>>>(Z + 2 * HIDD, C1, T,               HIDD);
    spmm64<<<nBlkSp, TB>>>(T,            HIDD, Hpre + 2 * HIDD, C1);
    k_clear_stats<<<1, C1>>>();
    bn_stats<<<512, C1>>>(Hpre);
    bn_final<<<1, C1>>>(g2, be2);
    bn_apply<<<nBlkAp, TB>>>(Hpre, Hn);

    // ---- final fc ----
    sgemm_k<<<gemmO, TB>>>(Hn, Wfc, out, NN, C1, HIDD, bfc);

    (void)in_sizes; (void)n_in; (void)out_size;
}

// round 2
// speedup vs baseline: 1.2267x; 1.2267x over previous
#include <cuda_runtime.h>
#include <cstdint>

#define NN   50000
#define EE   800000
#define FIN  128
#define HIDD 64
#define C1   192          // P*HID
#define EPSB 1e-5f
#define SCAN_B 196        // ceil(NN/256)

// ---------------- static device scratch (no allocations allowed) ----------------
__device__ int g_is64;
__device__ __align__(256) float g_Z   [(size_t)NN * C1];
__device__ __align__(256) float g_Hpre[(size_t)NN * C1];
__device__ __align__(256) float g_T   [(size_t)NN * HIDD];
__device__ int   g_cnt[NN];
__device__ int   g_rowptr[NN + 1];
__device__ int   g_pos[NN];
__device__ int   g_bsum[SCAN_B];
__device__ __align__(256) int   g_col[EE];
__device__ __align__(256) float g_w  [EE];
__device__ float g_dinv[NN];
__device__ float g_sum[C1];
__device__ float g_sq [C1];
__device__ float g_scale[C1];
__device__ float g_shift[C1];

// ---------------- edge index accessor (dtype-agnostic) ----------------
__device__ __forceinline__ int edge_at(const void* p, long long i) {
    if (g_is64) return (int)((const long long*)p)[i];
    return ((const int*)p)[i];
}

// Parallel dtype sniff: one warp checks 64 int64-view values; if data is really
// int32, a pair of random indices viewed as int64 is >= 2^32 almost surely.
__global__ void k_detect(const long long* e) {
    int lane = threadIdx.x;
    int bad = 0;
    #pragma unroll
    for (int l = 0; l < 2; l++) {
        long long v = e[lane + 32 * l];
        bad |= (v < 0 || v >= NN);
    }
    unsigned m = __ballot_sync(0xffffffffu, bad);
    if (lane == 0) g_is64 = (m == 0u);
}

// ---------------- graph preprocessing ----------------
__global__ void k_clear_cnt() {
    int i = blockIdx.x * blockDim.x + threadIdx.x;
    if (i < NN) g_cnt[i] = 0;
}

__global__ void k_count(const void* e) {
    int i = blockIdx.x * blockDim.x + threadIdx.x;
    if (i < EE) {
        int d = edge_at(e, (long long)EE + i);
        atomicAdd(&g_cnt[d], 1);
    }
}

// ---- 3-stage exclusive scan of g_cnt -> g_rowptr ----
__global__ void k_bsum() {                        // SCAN_B blocks x 256
    __shared__ int sh[256];
    int i = blockIdx.x * 256 + threadIdx.x;
    sh[threadIdx.x] = (i < NN) ? g_cnt[i] : 0;
    __syncthreads();
    for (int s = 128; s > 0; s >>= 1) {
        if (threadIdx.x < s) sh[threadIdx.x] += sh[threadIdx.x + s];
        __syncthreads();
    }
    if (threadIdx.x == 0) g_bsum[blockIdx.x] = sh[0];
}

__global__ void k_scan_bsum() {                   // 1 block x 256 (SCAN_B <= 256)
    __shared__ int sh[256];
    int t = threadIdx.x;
    int v = (t < SCAN_B) ? g_bsum[t] : 0;
    sh[t] = v;
    __syncthreads();
    for (int off = 1; off < 256; off <<= 1) {
        int tv = (t >= off) ? sh[t - off] : 0;
        __syncthreads();
        sh[t] += tv;
        __syncthreads();
    }
    if (t < SCAN_B) g_bsum[t] = sh[t] - v;        // exclusive
    if (t == 255) g_rowptr[NN] = sh[255];         // total = EE
}

__global__ void k_scan_final() {                  // SCAN_B blocks x 256
    __shared__ int sh[256];
    int t = threadIdx.x;
    int i = blockIdx.x * 256 + t;
    int v = (i < NN) ? g_cnt[i] : 0;
    sh[t] = v;
    __syncthreads();
    for (int off = 1; off < 256; off <<= 1) {
        int tv = (t >= off) ? sh[t - off] : 0;
        __syncthreads();
        sh[t] += tv;
        __syncthreads();
    }
    int excl = sh[t] - v + g_bsum[blockIdx.x];
    if (i < NN) { g_rowptr[i] = excl; g_pos[i] = excl; }
}

__global__ void k_dinv() {
    int i = blockIdx.x * blockDim.x + threadIdx.x;
    if (i < NN) g_dinv[i] = rsqrtf((float)g_cnt[i] + 1.0f);  // +1 self loop
}

__global__ void k_fill(const void* e) {
    int i = blockIdx.x * blockDim.x + threadIdx.x;
    if (i < EE) {
        int s = edge_at(e, i);
        int d = edge_at(e, (long long)EE + i);
        int p = atomicAdd(&g_pos[d], 1);
        g_col[p] = s;
        g_w[p]   = g_dinv[s] * g_dinv[d];
    }
}

// ---------------- fused SpMM over Z cols 64..191 (z1 -> Hpre+64, z2 -> T) -------
__global__ __launch_bounds__(256) void spmm128(
    const float* __restrict__ Z, float* __restrict__ H, float* __restrict__ T)
{
    int warp = (blockIdx.x * blockDim.x + threadIdx.x) >> 5;
    int lane = threadIdx.x & 31;
    if (warp >= NN) return;
    float dv = g_dinv[warp];
    float ws = dv * dv;
    const float4* zr = (const float4*)(Z + (size_t)warp * C1 + HIDD);
    float4 zv = zr[lane];
    float4 a;
    a.x = ws * zv.x; a.y = ws * zv.y; a.z = ws * zv.z; a.w = ws * zv.w;
    int e0 = g_rowptr[warp], e1 = g_rowptr[warp + 1];
    #pragma unroll 4
    for (int e = e0; e < e1; e++) {
        int c    = __ldg(&g_col[e]);
        float wt = __ldg(&g_w[e]);
        float4 v = ((const float4*)(Z + (size_t)c * C1 + HIDD))[lane];
        a.x = fmaf(wt, v.x, a.x);
        a.y = fmaf(wt, v.y, a.y);
        a.z = fmaf(wt, v.z, a.z);
        a.w = fmaf(wt, v.w, a.w);
    }
    if (lane < 16)
        ((float4*)(H + (size_t)warp * C1 + HIDD))[lane] = a;
    else
        ((float4*)(T + (size_t)warp * HIDD))[lane - 16] = a;
}

// ---------------- SpMM, 64 cols (for the second hop A * T) ----------------------
__global__ __launch_bounds__(256) void spmm64(
    const float* __restrict__ Z, int ldz,
    float* __restrict__ out, int ldo)
{
    int warp = (blockIdx.x * blockDim.x + threadIdx.x) >> 5;
    int lane = threadIdx.x & 31;
    if (warp >= NN) return;
    float dv = g_dinv[warp];
    float ws = dv * dv;
    float2 zv = ((const float2*)(Z + (size_t)warp * ldz))[lane];
    float ax = ws * zv.x, ay = ws * zv.y;
    int e0 = g_rowptr[warp], e1 = g_rowptr[warp + 1];
    #pragma unroll 4
    for (int e = e0; e < e1; e++) {
        int c    = __ldg(&g_col[e]);
        float wt = __ldg(&g_w[e]);
        float2 v = ((const float2*)(Z + (size_t)c * ldz))[lane];
        ax = fmaf(wt, v.x, ax);
        ay = fmaf(wt, v.y, ay);
    }
    float2 o; o.x = ax; o.y = ay;
    ((float2*)(out + (size_t)warp * ldo))[lane] = o;
}

// copy first 64 columns of Z (ld 192) into Hpre (ld 192)
__global__ void k_copy64(const float* __restrict__ Z, float* __restrict__ H) {
    int idx = blockIdx.x * blockDim.x + threadIdx.x;   // over NN*16 float4
    if (idx >= NN * 16) return;
    int r = idx >> 4, c4 = idx & 15;
    ((float4*)(H + (size_t)r * C1))[c4] = ((const float4*)(Z + (size_t)r * C1))[c4];
}

// ---------------- BatchNorm stats ----------------
__global__ void k_clear_stats() {
    int c = threadIdx.x;
    if (c < C1) { g_sum[c] = 0.f; g_sq[c] = 0.f; }
}

__global__ void bn_stats(const float* __restrict__ H) {
    int c = threadIdx.x;   // blockDim = 192
    float s = 0.f, q = 0.f;
    for (int r = blockIdx.x; r < NN; r += gridDim.x) {
        float v = H[(size_t)r * C1 + c];
        s += v;
        q = fmaf(v, v, q);
    }
    atomicAdd(&g_sum[c], s);
    atomicAdd(&g_sq[c], q);
}

__global__ void bn_final(const float* __restrict__ g, const float* __restrict__ be) {
    int c = threadIdx.x;
    if (c < C1) {
        float mu  = g_sum[c] * (1.0f / NN);
        float var = g_sq[c] * (1.0f / NN) - mu * mu;
        float inv = rsqrtf(var + EPSB);
        float sc  = inv * g[c];
        g_scale[c] = sc;
        g_shift[c] = be[c] - mu * sc;
    }
}

// ---------------- fp32 tiled GEMM with optional fused BN+ReLU on the A load -----
// C[M,NC] = act(A)[M,K] @ Bcat  where act(a)[r,c] = max(0, a*scale[c]+shift[c])
#define BM 128
#define BN 64
#define BK 16

__global__ __launch_bounds__(256) void sgemm_k(
    const float* __restrict__ A, const float* __restrict__ Bmat,
    float* __restrict__ C, int M, int K, int NC,
    const float* __restrict__ bias,
    const float* __restrict__ scale, const float* __restrict__ shift)
{
    __shared__ float As[BK][BM + 4];
    __shared__ float Bs[BK][BN];
    int p = blockIdx.y;
    const float* Bp = Bmat + (size_t)p * K * BN;   // W[p] is [K,64] row-major
    int rowBase = blockIdx.x * BM;
    int tid = threadIdx.x;
    int tx = tid & 15;     // column group 0..15
    int ty = tid >> 4;     // row group 0..15

    float acc[8][4];
    #pragma unroll
    for (int i = 0; i < 8; i++)
        #pragma unroll
        for (int j = 0; j < 4; j++) acc[i][j] = 0.f;

    for (int k0 = 0; k0 < K; k0 += BK) {
        // load A tile: 512 float4 slots, 2 per thread
        #pragma unroll
        for (int l = 0; l < 2; l++) {
            int slot = tid + l * 256;
            int ar  = slot >> 2;
            int ac4 = slot & 3;
            int grow = rowBase + ar;
            float4 v = make_float4(0.f, 0.f, 0.f, 0.f);
            if (grow < M)
                v = *(const float4*)(A + (size_t)grow * K + k0 + ac4 * 4);
            if (scale) {
                int kc = k0 + ac4 * 4;
                v.x = fmaxf(0.f, fmaf(v.x, scale[kc + 0], shift[kc + 0]));
                v.y = fmaxf(0.f, fmaf(v.y, scale[kc + 1], shift[kc + 1]));
                v.z = fmaxf(0.f, fmaf(v.z, scale[kc + 2], shift[kc + 2]));
                v.w = fmaxf(0.f, fmaf(v.w, scale[kc + 3], shift[kc + 3]));
            }
            As[ac4 * 4 + 0][ar] = v.x;
            As[ac4 * 4 + 1][ar] = v.y;
            As[ac4 * 4 + 2][ar] = v.z;
            As[ac4 * 4 + 3][ar] = v.w;
        }
        // load B tile: 256 float4 slots, 1 per thread
        {
            int br  = tid >> 4;
            int bc4 = tid & 15;
            float4 v = *(const float4*)(Bp + (size_t)(k0 + br) * BN + bc4 * 4);
            *(float4*)&Bs[br][bc4 * 4] = v;
        }
        __syncthreads();
        #pragma unroll
        for (int kk = 0; kk < BK; kk++) {
            float4 a0 = *(const float4*)&As[kk][ty * 8];
            float4 a1 = *(const float4*)&As[kk][ty * 8 + 4];
            float4 b0 = *(const float4*)&Bs[kk][tx * 4];
            float a[8] = {a0.x, a0.y, a0.z, a0.w, a1.x, a1.y, a1.z, a1.w};
            float b[4] = {b0.x, b0.y, b0.z, b0.w};
            #pragma unroll
            for (int i = 0; i < 8; i++)
                #pragma unroll
                for (int j = 0; j < 4; j++)
                    acc[i][j] = fmaf(a[i], b[j], acc[i][j]);
        }
        __syncthreads();
    }
    int colBase = p * BN + tx * 4;
    float4 bb = make_float4(0.f, 0.f, 0.f, 0.f);
    if (bias) {
        bb.x = bias[colBase + 0]; bb.y = bias[colBase + 1];
        bb.z = bias[colBase + 2]; bb.w = bias[colBase + 3];
    }
    #pragma unroll
    for (int i = 0; i < 8; i++) {
        int r = rowBase + ty * 8 + i;
        if (r < M) {
            float4 o;
            o.x = acc[i][0] + bb.x;
            o.y = acc[i][1] + bb.y;
            o.z = acc[i][2] + bb.z;
            o.w = acc[i][3] + bb.w;
            *(float4*)(C + (size_t)r * NC + colBase) = o;
        }
    }
}

// ---------------- host launch ----------------
extern "C" void kernel_launch(void* const* d_in, const int* in_sizes, int n_in,
                              void* d_out, int out_size) {
    const float* x   = (const float*)d_in[0];
    const void*  ei  = d_in[1];
    const float* W1  = (const float*)d_in[2];
    // d_in[3] = B1  (absorbed by BatchNorm — mathematically a no-op)
    const float* g1  = (const float*)d_in[4];
    const float* be1 = (const float*)d_in[5];
    const float* W2  = (const float*)d_in[6];
    // d_in[7] = B2  (absorbed by BatchNorm)
    const float* g2  = (const float*)d_in[8];
    const float* be2 = (const float*)d_in[9];
    const float* Wfc = (const float*)d_in[10];
    const float* bfc = (const float*)d_in[11];
    float* out = (float*)d_out;

    float *Z, *Hpre, *T, *Sc, *Sh;
    cudaGetSymbolAddress((void**)&Z,    g_Z);
    cudaGetSymbolAddress((void**)&Hpre, g_Hpre);
    cudaGetSymbolAddress((void**)&T,    g_T);
    cudaGetSymbolAddress((void**)&Sc,   g_scale);
    cudaGetSymbolAddress((void**)&Sh,   g_shift);

    const int TB = 256;
    const int nBlkN   = (NN + TB - 1) / TB;
    const int nBlkE   = (EE + TB - 1) / TB;
    const int nBlkSp  = (NN + 7) / 8;            // warp per row, 8 warps/block
    const int nBlkCp  = (NN * 16 + TB - 1) / TB;
    const dim3 gemmG((NN + BM - 1) / BM, 3);
    const dim3 gemmO((NN + BM - 1) / BM, 1);

    // preprocessing: dtype sniff, degrees, CSR, norms
    k_detect<<<1, 32>>>((const long long*)ei);
    k_clear_cnt<<<nBlkN, TB>>>();
    k_count<<<nBlkE, TB>>>(ei);
    k_bsum<<<SCAN_B, 256>>>();
    k_scan_bsum<<<1, 256>>>();
    k_scan_final<<<SCAN_B, 256>>>();
    k_dinv<<<nBlkN, TB>>>();
    k_fill<<<nBlkE, TB>>>(ei);

    // ---- layer 1:  Z = x @ [W1_0|W1_1|W1_2]  then propagate 64-wide slices ----
    sgemm_k<<<gemmG, TB>>>(x, W1, Z, NN, FIN, C1, nullptr, nullptr, nullptr);
    k_copy64<<<nBlkCp, TB>>>(Z, Hpre);                       // power 0
    spmm128<<<nBlkSp, TB>>>(Z, Hpre, T);                     // A z1 -> Hpre+64, A z2 -> T
    spmm64<<<nBlkSp, TB>>>(T, HIDD, Hpre + 2 * HIDD, C1);    // A^2 z2 -> Hpre+128
    k_clear_stats<<<1, C1>>>();
    bn_stats<<<512, C1>>>(Hpre);
    bn_final<<<1, C1>>>(g1, be1);

    // ---- layer 2 (BN1+ReLU fused into the A load) ----
    sgemm_k<<<gemmG, TB>>>(Hpre, W2, Z, NN, C1, C1, nullptr, Sc, Sh);
    k_copy64<<<nBlkCp, TB>>>(Z, Hpre);
    spmm128<<<nBlkSp, TB>>>(Z, Hpre, T);
    spmm64<<<nBlkSp, TB>>>(T, HIDD, Hpre + 2 * HIDD, C1);
    k_clear_stats<<<1, C1>>>();
    bn_stats<<<512, C1>>>(Hpre);
    bn_final<<<1, C1>>>(g2, be2);

    // ---- final fc (BN2+ReLU fused into the A load) ----
    sgemm_k<<<gemmO, TB>>>(Hpre, Wfc, out, NN, C1, HIDD, bfc, Sc, Sh);

    (void)in_sizes; (void)n_in; (void)out_size;
}

// round 5
// speedup vs baseline: 1.3245x; 1.0797x over previous
#include <cuda_runtime.h>
#include <cstdint>

#define NN   50000
#define EE   800000
#define FIN  128
#define HIDD 64
#define C1   192          // P*HID
#define EPSB 1e-5f
#define SCAN_B 196        // ceil(NN/256)

// ---------------- static device scratch (no allocations allowed) ----------------
__device__ int g_is64;
__device__ __align__(256) float g_Z   [(size_t)NN * C1];
__device__ __align__(256) float g_Hpre[(size_t)NN * C1];
__device__ __align__(256) float g_H2  [(size_t)NN * C1];
__device__ __align__(256) float g_T   [(size_t)NN * HIDD];
__device__ int   g_cnt[NN];
__device__ int   g_rowptr[NN + 1];
__device__ int   g_pos[NN];
__device__ int   g_bsum[SCAN_B];
__device__ __align__(256) int   g_col[EE];
__device__ __align__(256) float g_w  [EE];
__device__ float g_dinv[NN];
__device__ float g_sum[C1];
__device__ float g_sq [C1];
__device__ float g_scale[C1];
__device__ float g_shift[C1];

// ---------------- edge index accessor (dtype-agnostic) ----------------
__device__ __forceinline__ int edge_at(const void* p, long long i) {
    if (g_is64) return (int)((const long long*)p)[i];
    return ((const int*)p)[i];
}

__global__ void k_detect(const long long* e) {
    int lane = threadIdx.x;
    int bad = 0;
    #pragma unroll
    for (int l = 0; l < 2; l++) {
        long long v = e[lane + 32 * l];
        bad |= (v < 0 || v >= NN);
    }
    unsigned m = __ballot_sync(0xffffffffu, bad);
    if (lane == 0) g_is64 = (m == 0u);
}

// ---------------- graph preprocessing ----------------
__global__ void k_clear_cnt() {
    int i = blockIdx.x * blockDim.x + threadIdx.x;
    if (i < NN) g_cnt[i] = 0;
}

__global__ void k_count(const void* e) {
    int i = blockIdx.x * blockDim.x + threadIdx.x;
    if (i < EE) {
        int d = edge_at(e, (long long)EE + i);
        atomicAdd(&g_cnt[d], 1);
    }
}

__global__ void k_bsum() {
    __shared__ int sh[256];
    int i = blockIdx.x * 256 + threadIdx.x;
    sh[threadIdx.x] = (i < NN) ? g_cnt[i] : 0;
    __syncthreads();
    for (int s = 128; s > 0; s >>= 1) {
        if (threadIdx.x < s) sh[threadIdx.x] += sh[threadIdx.x + s];
        __syncthreads();
    }
    if (threadIdx.x == 0) g_bsum[blockIdx.x] = sh[0];
}

__global__ void k_scan_bsum() {
    __shared__ int sh[256];
    int t = threadIdx.x;
    int v = (t < SCAN_B) ? g_bsum[t] : 0;
    sh[t] = v;
    __syncthreads();
    for (int off = 1; off < 256; off <<= 1) {
        int tv = (t >= off) ? sh[t - off] : 0;
        __syncthreads();
        sh[t] += tv;
        __syncthreads();
    }
    if (t < SCAN_B) g_bsum[t] = sh[t] - v;
    if (t == 255) g_rowptr[NN] = sh[255];
}

__global__ void k_scan_final() {
    __shared__ int sh[256];
    int t = threadIdx.x;
    int i = blockIdx.x * 256 + t;
    int v = (i < NN) ? g_cnt[i] : 0;
    sh[t] = v;
    __syncthreads();
    for (int off = 1; off < 256; off <<= 1) {
        int tv = (t >= off) ? sh[t - off] : 0;
        __syncthreads();
        sh[t] += tv;
        __syncthreads();
    }
    int excl = sh[t] - v + g_bsum[blockIdx.x];
    if (i < NN) { g_rowptr[i] = excl; g_pos[i] = excl; }
}

__global__ void k_dinv() {
    int i = blockIdx.x * blockDim.x + threadIdx.x;
    if (i < NN) g_dinv[i] = rsqrtf((float)g_cnt[i] + 1.0f);
}

__global__ void k_fill(const void* e) {
    int i = blockIdx.x * blockDim.x + threadIdx.x;
    if (i < EE) {
        int s = edge_at(e, i);
        int d = edge_at(e, (long long)EE + i);
        int p = atomicAdd(&g_pos[d], 1);
        g_col[p] = s;
        g_w[p]   = g_dinv[s] * g_dinv[d];
    }
}

// ---------------- fused SpMM over Z cols 64..191 (z1 -> H+64, z2 -> T) -------
__global__ __launch_bounds__(256) void spmm128(
    const float* __restrict__ Z, float* __restrict__ H, float* __restrict__ T)
{
    int warp = (blockIdx.x * blockDim.x + threadIdx.x) >> 5;
    int lane = threadIdx.x & 31;
    if (warp >= NN) return;
    float dv = g_dinv[warp];
    float ws = dv * dv;
    float4 zv = ((const float4*)(Z + (size_t)warp * C1 + HIDD))[lane];
    float4 a;
    a.x = ws * zv.x; a.y = ws * zv.y; a.z = ws * zv.z; a.w = ws * zv.w;
    int e0 = g_rowptr[warp], e1 = g_rowptr[warp + 1];
    #pragma unroll 4
    for (int e = e0; e < e1; e++) {
        int c    = __ldg(&g_col[e]);
        float wt = __ldg(&g_w[e]);
        float4 v = ((const float4*)(Z + (size_t)c * C1 + HIDD))[lane];
        a.x = fmaf(wt, v.x, a.x);
        a.y = fmaf(wt, v.y, a.y);
        a.z = fmaf(wt, v.z, a.z);
        a.w = fmaf(wt, v.w, a.w);
    }
    if (lane < 16)
        ((float4*)(H + (size_t)warp * C1 + HIDD))[lane] = a;
    else
        ((float4*)(T + (size_t)warp * HIDD))[lane - 16] = a;
}

__global__ __launch_bounds__(256) void spmm64(
    const float* __restrict__ Z, int ldz,
    float* __restrict__ out, int ldo)
{
    int warp = (blockIdx.x * blockDim.x + threadIdx.x) >> 5;
    int lane = threadIdx.x & 31;
    if (warp >= NN) return;
    float dv = g_dinv[warp];
    float ws = dv * dv;
    float2 zv = ((const float2*)(Z + (size_t)warp * ldz))[lane];
    float ax = ws * zv.x, ay = ws * zv.y;
    int e0 = g_rowptr[warp], e1 = g_rowptr[warp + 1];
    #pragma unroll 4
    for (int e = e0; e < e1; e++) {
        int c    = __ldg(&g_col[e]);
        float wt = __ldg(&g_w[e]);
        float2 v = ((const float2*)(Z + (size_t)c * ldz))[lane];
        ax = fmaf(wt, v.x, ax);
        ay = fmaf(wt, v.y, ay);
    }
    float2 o; o.x = ax; o.y = ay;
    ((float2*)(out + (size_t)warp * ldo))[lane] = o;
}

// ---------------- BatchNorm stats ----------------
__global__ void k_clear_stats() {
    int c = threadIdx.x;
    if (c < C1) { g_sum[c] = 0.f; g_sq[c] = 0.f; }
}

__global__ void bn_stats(const float* __restrict__ H) {
    int c = threadIdx.x;
    float s = 0.f, q = 0.f;
    for (int r = blockIdx.x; r < NN; r += gridDim.x) {
        float v = H[(size_t)r * C1 + c];
        s += v;
        q = fmaf(v, v, q);
    }
    atomicAdd(&g_sum[c], s);
    atomicAdd(&g_sq[c], q);
}

__global__ void bn_final(const float* __restrict__ g, const float* __restrict__ be) {
    int c = threadIdx.x;
    if (c < C1) {
        float mu  = g_sum[c] * (1.0f / NN);
        float var = g_sq[c] * (1.0f / NN) - mu * mu;
        float inv = rsqrtf(var + EPSB);
        float sc  = inv * g[c];
        g_scale[c] = sc;
        g_shift[c] = be[c] - mu * sc;
    }
}

// ---------------- tf32 tensor-core GEMM with split-precision compensation -------
// C[M,NC](+dup) = act(A)[M,K] @ W[p][K,64] (+bias),  act = BN+ReLU if scale given
#define BM 128
#define BN 64
#define BK 32
#define ASTRIDE 36   // (4r+c)%32 unique -> conflict-free A frag loads
#define BSTRIDE 72   // (8k+n)%32 unique -> conflict-free B frag loads

__device__ __forceinline__ uint32_t f2tf(float x) {
    uint32_t r;
    asm("cvt.rna.tf32.f32 %0, %1;" : "=r"(r) : "f"(x));
    return r;
}

__device__ __forceinline__ void mma_tf32(float* d, const uint32_t* a, const uint32_t* b) {
    asm volatile(
        "mma.sync.aligned.m16n8k8.row.col.f32.tf32.tf32.f32 "
        "{%0,%1,%2,%3},{%4,%5,%6,%7},{%8,%9},{%0,%1,%2,%3};\n"
        : "+f"(d[0]), "+f"(d[1]), "+f"(d[2]), "+f"(d[3])
        : "r"(a[0]), "r"(a[1]), "r"(a[2]), "r"(a[3]), "r"(b[0]), "r"(b[1]));
}

__global__ __launch_bounds__(256, 2) void tgemm(
    const float* __restrict__ A, const float* __restrict__ Bmat,
    float* __restrict__ C, int M, int K, int NC,
    const float* __restrict__ bias,
    const float* __restrict__ scale, const float* __restrict__ shift,
    float* __restrict__ dup)          // if non-null and p==0: also store there (ld C1)
{
    __shared__ float As[BM * ASTRIDE];
    __shared__ float Bs[BK * BSTRIDE];
    int p = blockIdx.y;
    const float* Bp = Bmat + (size_t)p * K * BN;
    int rowBase = blockIdx.x * BM;
    int tid  = threadIdx.x;
    int lane = tid & 31;
    int w    = tid >> 5;
    int wm   = w & 3;         // 0..3 over M
    int wn   = w >> 2;        // 0..1 over N
    int lr   = lane >> 2;     // 0..7
    int lc   = lane & 3;      // 0..3

    float acc[2][4][4];
    #pragma unroll
    for (int mt = 0; mt < 2; mt++)
        #pragma unroll
        for (int nt = 0; nt < 4; nt++)
            #pragma unroll
            for (int i = 0; i < 4; i++) acc[mt][nt][i] = 0.f;

    for (int k0 = 0; k0 < K; k0 += BK) {
        // A tile: 128x32 = 1024 float4 slots, 4 per thread
        #pragma unroll
        for (int l = 0; l < 4; l++) {
            int slot = tid + l * 256;
            int ar  = slot >> 3;
            int ac4 = slot & 7;
            int grow = rowBase + ar;
            float4 v = make_float4(0.f, 0.f, 0.f, 0.f);
            if (grow < M)
                v = *(const float4*)(A + (size_t)grow * K + k0 + ac4 * 4);
            if (scale) {
                int kc = k0 + ac4 * 4;
                v.x = fmaxf(0.f, fmaf(v.x, scale[kc + 0], shift[kc + 0]));
                v.y = fmaxf(0.f, fmaf(v.y, scale[kc + 1], shift[kc + 1]));
                v.z = fmaxf(0.f, fmaf(v.z, scale[kc + 2], shift[kc + 2]));
                v.w = fmaxf(0.f, fmaf(v.w, scale[kc + 3], shift[kc + 3]));
            }
            float* d = &As[ar * ASTRIDE + ac4 * 4];
            d[0] = v.x; d[1] = v.y; d[2] = v.z; d[3] = v.w;
        }
        // B tile: 32x64 = 512 float4 slots, 2 per thread
        #pragma unroll
        for (int l = 0; l < 2; l++) {
            int slot = tid + l * 256;
            int bk  = slot >> 4;
            int bn4 = slot & 15;
            float4 v = *(const float4*)(Bp + (size_t)(k0 + bk) * BN + bn4 * 4);
            float* d = &Bs[bk * BSTRIDE + bn4 * 4];
            d[0] = v.x; d[1] = v.y; d[2] = v.z; d[3] = v.w;
        }
        __syncthreads();

        #pragma unroll
        for (int ks = 0; ks < 4; ks++) {
            int kb = ks * 8;
            uint32_t ahi[2][4], alo[2][4];
            #pragma unroll
            for (int mt = 0; mt < 2; mt++) {
                int r0 = wm * 32 + mt * 16 + lr;
                float a0 = As[r0 * ASTRIDE + kb + lc];
                float a1 = As[(r0 + 8) * ASTRIDE + kb + lc];
                float a2 = As[r0 * ASTRIDE + kb + lc + 4];
                float a3 = As[(r0 + 8) * ASTRIDE + kb + lc + 4];
                ahi[mt][0] = f2tf(a0); alo[mt][0] = f2tf(a0 - __uint_as_float(ahi[mt][0]));
                ahi[mt][1] = f2tf(a1); alo[mt][1] = f2tf(a1 - __uint_as_float(ahi[mt][1]));
                ahi[mt][2] = f2tf(a2); alo[mt][2] = f2tf(a2 - __uint_as_float(ahi[mt][2]));
                ahi[mt][3] = f2tf(a3); alo[mt][3] = f2tf(a3 - __uint_as_float(ahi[mt][3]));
            }
            uint32_t bhi[4][2], blo[4][2];
            #pragma unroll
            for (int nt = 0; nt < 4; nt++) {
                int n0 = wn * 32 + nt * 8 + lr;
                float b0 = Bs[(kb + lc) * BSTRIDE + n0];
                float b1 = Bs[(kb + lc + 4) * BSTRIDE + n0];
                bhi[nt][0] = f2tf(b0); blo[nt][0] = f2tf(b0 - __uint_as_float(bhi[nt][0]));
                bhi[nt][1] = f2tf(b1); blo[nt][1] = f2tf(b1 - __uint_as_float(bhi[nt][1]));
            }
            #pragma unroll
            for (int mt = 0; mt < 2; mt++)
                #pragma unroll
                for (int nt = 0; nt < 4; nt++) {
                    mma_tf32(acc[mt][nt], ahi[mt], bhi[nt]);
                    mma_tf32(acc[mt][nt], ahi[mt], blo[nt]);
                    mma_tf32(acc[mt][nt], alo[mt], bhi[nt]);
                }
        }
        __syncthreads();
    }

    bool dodup = (dup != nullptr) && (p == 0);
    #pragma unroll
    for (int mt = 0; mt < 2; mt++) {
        #pragma unroll
        for (int nt = 0; nt < 4; nt++) {
            int ncol = wn * 32 + nt * 8 + lc * 2;      // col within the 64-block
            int gcol = p * BN + ncol;                  // col within C
            float bx = 0.f, by = 0.f;
            if (bias) { bx = bias[ncol]; by = bias[ncol + 1]; }
            int r = rowBase + wm * 32 + mt * 16 + lr;
            if (r < M) {
                float2 o; o.x = acc[mt][nt][0] + bx; o.y = acc[mt][nt][1] + by;
                *(float2*)(C + (size_t)r * NC + gcol) = o;
                if (dodup) *(float2*)(dup + (size_t)r * C1 + gcol) = o;
            }
            if (r + 8 < M) {
                float2 o; o.x = acc[mt][nt][2] + bx; o.y = acc[mt][nt][3] + by;
                *(float2*)(C + (size_t)(r + 8) * NC + gcol) = o;
                if (dodup) *(float2*)(dup + (size_t)(r + 8) * C1 + gcol) = o;
            }
        }
    }
}

// ---------------- host launch ----------------
extern "C" void kernel_launch(void* const* d_in, const int* in_sizes, int n_in,
                              void* d_out, int out_size) {
    const float* x   = (const float*)d_in[0];
    const void*  ei  = d_in[1];
    const float* W1  = (const float*)d_in[2];
    // d_in[3] = B1 (absorbed by BatchNorm)
    const float* g1  = (const float*)d_in[4];
    const float* be1 = (const float*)d_in[5];
    const float* W2  = (const float*)d_in[6];
    // d_in[7] = B2 (absorbed by BatchNorm)
    const float* g2  = (const float*)d_in[8];
    const float* be2 = (const float*)d_in[9];
    const float* Wfc = (const float*)d_in[10];
    const float* bfc = (const float*)d_in[11];
    float* out = (float*)d_out;

    float *Z, *Hpre, *H2, *T, *Sc, *Sh;
    cudaGetSymbolAddress((void**)&Z,    g_Z);
    cudaGetSymbolAddress((void**)&Hpre, g_Hpre);
    cudaGetSymbolAddress((void**)&H2,   g_H2);
    cudaGetSymbolAddress((void**)&T,    g_T);
    cudaGetSymbolAddress((void**)&Sc,   g_scale);
    cudaGetSymbolAddress((void**)&Sh,   g_shift);

    const int TB = 256;
    const int nBlkN  = (NN + TB - 1) / TB;
    const int nBlkE  = (EE + TB - 1) / TB;
    const int nBlkSp = (NN + 7) / 8;
    const dim3 gemmG((NN + BM - 1) / BM, 3);
    const dim3 gemmO((NN + BM - 1) / BM, 1);

    // preprocessing
    k_detect<<<1, 32>>>((const long long*)ei);
    k_clear_cnt<<<nBlkN, TB>>>();
    k_count<<<nBlkE, TB>>>(ei);
    k_bsum<<<SCAN_B, 256>>>();
    k_scan_bsum<<<1, 256>>>();
    k_scan_final<<<SCAN_B, 256>>>();
    k_dinv<<<nBlkN, TB>>>();
    k_fill<<<nBlkE, TB>>>(ei);

    // ---- layer 1:  A=x  C=Z  dup=Hpre (no aliasing: A is the input tensor) ----
    tgemm<<<gemmG, TB>>>(x, W1, Z, NN, FIN, C1, nullptr, nullptr, nullptr, Hpre);
    spmm128<<<nBlkSp, TB>>>(Z, Hpre, T);
    spmm64<<<nBlkSp, TB>>>(T, HIDD, Hpre + 2 * HIDD, C1);
    k_clear_stats<<<1, C1>>>();
    bn_stats<<<512, C1>>>(Hpre);
    bn_final<<<1, C1>>>(g1, be1);

    // ---- layer 2:  A=Hpre  C=Z  dup=H2 (dup target != A buffer -> no race) ----
    tgemm<<<gemmG, TB>>>(Hpre, W2, Z, NN, C1, C1, nullptr, Sc, Sh, H2);
    spmm128<<<nBlkSp, TB>>>(Z, H2, T);
    spmm64<<<nBlkSp, TB>>>(T, HIDD, H2 + 2 * HIDD, C1);
    k_clear_stats<<<1, C1>>>();
    bn_stats<<<512, C1>>>(H2);
    bn_final<<<1, C1>>>(g2, be2);

    // ---- final fc:  A=H2 -> out ----
    tgemm<<<gemmO, TB>>>(H2, Wfc, out, NN, C1, HIDD, bfc, Sc, Sh, nullptr);

    (void)in_sizes; (void)n_in; (void)out_size;
}

// round 6
// speedup vs baseline: 1.4677x; 1.1081x over previous
#include <cuda_runtime.h>
#include <cuda_bf16.h>
#include <cstdint>

#define NN   50000
#define EE   800000
#define FIN  128
#define HIDD 64
#define C1   192          // P*HID
#define EPSB 1e-5f
#define SCAN_B 196        // ceil(NN/256)

// ---------------- static device scratch (no allocations allowed) ----------------
__device__ int g_is64;
__device__ __align__(256) float g_Z   [(size_t)NN * C1];
__device__ __align__(256) float g_Hpre[(size_t)NN * C1];
__device__ __align__(256) float g_H2  [(size_t)NN * C1];
__device__ __align__(256) float g_T   [(size_t)NN * HIDD];
__device__ int   g_cnt[NN];
__device__ int   g_rowptr[NN + 1];
__device__ int   g_pos[NN];
__device__ int   g_bsum[SCAN_B];
__device__ __align__(256) int   g_col[EE];
__device__ __align__(256) float g_w  [EE];
__device__ float g_dinv[NN];
__device__ float g_sum[C1];
__device__ float g_sq [C1];
__device__ float g_scale[C1];
__device__ float g_shift[C1];

// ---------------- edge index accessor (dtype-agnostic) ----------------
__device__ __forceinline__ int edge_at(const void* p, long long i) {
    if (g_is64) return (int)((const long long*)p)[i];
    return ((const int*)p)[i];
}

__global__ void k_detect(const long long* e) {
    int lane = threadIdx.x;
    int bad = 0;
    #pragma unroll
    for (int l = 0; l < 2; l++) {
        long long v = e[lane + 32 * l];
        bad |= (v < 0 || v >= NN);
    }
    unsigned m = __ballot_sync(0xffffffffu, bad);
    if (lane == 0) g_is64 = (m == 0u);
}

// ---------------- graph preprocessing ----------------
__global__ void k_count(const void* e) {
    int i = blockIdx.x * blockDim.x + threadIdx.x;
    if (i < EE) {
        int d = edge_at(e, (long long)EE + i);
        atomicAdd(&g_cnt[d], 1);
    }
}

__global__ void k_bsum() {
    __shared__ int sh[256];
    int i = blockIdx.x * 256 + threadIdx.x;
    sh[threadIdx.x] = (i < NN) ? g_cnt[i] : 0;
    __syncthreads();
    for (int s = 128; s > 0; s >>= 1) {
        if (threadIdx.x < s) sh[threadIdx.x] += sh[threadIdx.x + s];
        __syncthreads();
    }
    if (threadIdx.x == 0) g_bsum[blockIdx.x] = sh[0];
}

__global__ void k_scan_bsum() {
    __shared__ int sh[256];
    int t = threadIdx.x;
    int v = (t < SCAN_B) ? g_bsum[t] : 0;
    sh[t] = v;
    __syncthreads();
    for (int off = 1; off < 256; off <<= 1) {
        int tv = (t >= off) ? sh[t - off] : 0;
        __syncthreads();
        sh[t] += tv;
        __syncthreads();
    }
    if (t < SCAN_B) g_bsum[t] = sh[t] - v;
    if (t == 255) g_rowptr[NN] = sh[255];
}

__global__ void k_scan_final() {
    __shared__ int sh[256];
    int t = threadIdx.x;
    int i = blockIdx.x * 256 + t;
    int v = (i < NN) ? g_cnt[i] : 0;
    sh[t] = v;
    __syncthreads();
    for (int off = 1; off < 256; off <<= 1) {
        int tv = (t >= off) ? sh[t - off] : 0;
        __syncthreads();
        sh[t] += tv;
        __syncthreads();
    }
    int excl = sh[t] - v + g_bsum[blockIdx.x];
    if (i < NN) { g_rowptr[i] = excl; g_pos[i] = excl; }
}

__global__ void k_dinv() {
    int i = blockIdx.x * blockDim.x + threadIdx.x;
    if (i < NN) g_dinv[i] = rsqrtf((float)g_cnt[i] + 1.0f);
}

__global__ void k_fill(const void* e) {
    int i = blockIdx.x * blockDim.x + threadIdx.x;
    if (i < EE) {
        int s = edge_at(e, i);
        int d = edge_at(e, (long long)EE + i);
        int p = atomicAdd(&g_pos[d], 1);
        g_col[p] = s;
        g_w[p]   = g_dinv[s] * g_dinv[d];
    }
}

// ---------------- fused SpMM over Z cols 64..191 (z1 -> H+64, z2 -> T) -------
__global__ __launch_bounds__(256) void spmm128(
    const float* __restrict__ Z, float* __restrict__ H, float* __restrict__ T)
{
    int warp = (blockIdx.x * blockDim.x + threadIdx.x) >> 5;
    int lane = threadIdx.x & 31;
    if (warp >= NN) return;
    float dv = g_dinv[warp];
    float ws = dv * dv;
    float4 zv = ((const float4*)(Z + (size_t)warp * C1 + HIDD))[lane];
    float4 a;
    a.x = ws * zv.x; a.y = ws * zv.y; a.z = ws * zv.z; a.w = ws * zv.w;
    int e0 = g_rowptr[warp], e1 = g_rowptr[warp + 1];
    #pragma unroll 4
    for (int e = e0; e < e1; e++) {
        int c    = __ldg(&g_col[e]);
        float wt = __ldg(&g_w[e]);
        float4 v = ((const float4*)(Z + (size_t)c * C1 + HIDD))[lane];
        a.x = fmaf(wt, v.x, a.x);
        a.y = fmaf(wt, v.y, a.y);
        a.z = fmaf(wt, v.z, a.z);
        a.w = fmaf(wt, v.w, a.w);
    }
    if (lane < 16)
        ((float4*)(H + (size_t)warp * C1 + HIDD))[lane] = a;
    else
        ((float4*)(T + (size_t)warp * HIDD))[lane - 16] = a;
}

__global__ __launch_bounds__(256) void spmm64(
    const float* __restrict__ Z, int ldz,
    float* __restrict__ out, int ldo)
{
    int warp = (blockIdx.x * blockDim.x + threadIdx.x) >> 5;
    int lane = threadIdx.x & 31;
    if (warp >= NN) return;
    float dv = g_dinv[warp];
    float ws = dv * dv;
    float2 zv = ((const float2*)(Z + (size_t)warp * ldz))[lane];
    float ax = ws * zv.x, ay = ws * zv.y;
    int e0 = g_rowptr[warp], e1 = g_rowptr[warp + 1];
    #pragma unroll 4
    for (int e = e0; e < e1; e++) {
        int c    = __ldg(&g_col[e]);
        float wt = __ldg(&g_w[e]);
        float2 v = ((const float2*)(Z + (size_t)c * ldz))[lane];
        ax = fmaf(wt, v.x, ax);
        ay = fmaf(wt, v.y, ay);
    }
    float2 o; o.x = ax; o.y = ay;
    ((float2*)(out + (size_t)warp * ldo))[lane] = o;
}

// ---------------- BatchNorm stats ----------------
__global__ void bn_stats(const float* __restrict__ H) {
    int c = threadIdx.x;
    float s = 0.f, q = 0.f;
    for (int r = blockIdx.x; r < NN; r += gridDim.x) {
        float v = H[(size_t)r * C1 + c];
        s += v;
        q = fmaf(v, v, q);
    }
    atomicAdd(&g_sum[c], s);
    atomicAdd(&g_sq[c], q);
}

__global__ void bn_final(const float* __restrict__ g, const float* __restrict__ be) {
    int c = threadIdx.x;
    if (c < C1) {
        float mu  = g_sum[c] * (1.0f / NN);
        float var = g_sq[c] * (1.0f / NN) - mu * mu;
        float inv = rsqrtf(var + EPSB);
        float sc  = inv * g[c];
        g_scale[c] = sc;
        g_shift[c] = be[c] - mu * sc;
    }
}

// ------------- bf16 split-2 tensor-core GEMM (m16n8k16, 3-term compensation) ----
// C[M,NC](+dup) = act(A)[M,K] @ W[p][K,64] (+bias),  act = BN+ReLU if scale given
// A = Ahi + Alo (bf16 each);  D = Ahi*Bhi + Ahi*Blo + Alo*Bhi  (err ~2^-16)
#define BM 128
#define BN 64
#define BK 32
#define KP 16        // k-pairs per BK block
#define AST 20       // As row stride (uint32): (20r+kp)%32 unique over r0..7,kp lc-pattern
#define BST 72       // Bs kp-row stride (uint32): (8kp+n)%32 unique

__device__ __forceinline__ uint32_t pack_bf16(float x, float y) {
    __nv_bfloat162 t;
    t.x = __float2bfloat16_rn(x);
    t.y = __float2bfloat16_rn(y);
    return *reinterpret_cast<uint32_t*>(&t);
}
__device__ __forceinline__ float bf_hi_f(float x) {
    return __bfloat162float(__float2bfloat16_rn(x));
}

__device__ __forceinline__ void mma_bf16(float* d, const uint32_t* a, const uint32_t* b) {
    asm volatile(
        "mma.sync.aligned.m16n8k16.row.col.f32.bf16.bf16.f32 "
        "{%0,%1,%2,%3},{%4,%5,%6,%7},{%8,%9},{%0,%1,%2,%3};\n"
        : "+f"(d[0]), "+f"(d[1]), "+f"(d[2]), "+f"(d[3])
        : "r"(a[0]), "r"(a[1]), "r"(a[2]), "r"(a[3]), "r"(b[0]), "r"(b[1]));
}

__global__ __launch_bounds__(256, 2) void tgemm(
    const float* __restrict__ A, const float* __restrict__ Bmat,
    float* __restrict__ C, int M, int K, int NC,
    const float* __restrict__ bias,
    const float* __restrict__ scale, const float* __restrict__ shift,
    float* __restrict__ dup)          // if non-null and p==0: also store there (ld C1)
{
    __shared__ uint32_t AsH[BM * AST];
    __shared__ uint32_t AsL[BM * AST];
    __shared__ uint32_t BsH[KP * BST];
    __shared__ uint32_t BsL[KP * BST];
    int p = blockIdx.y;
    const float* Bp = Bmat + (size_t)p * K * BN;
    int rowBase = blockIdx.x * BM;
    int tid  = threadIdx.x;
    int lane = tid & 31;
    int w    = tid >> 5;
    int wm   = w & 3;         // 0..3 over M
    int wn   = w >> 2;        // 0..1 over N
    int lr   = lane >> 2;     // 0..7
    int lc   = lane & 3;      // 0..3

    float acc[2][4][4];
    #pragma unroll
    for (int mt = 0; mt < 2; mt++)
        #pragma unroll
        for (int nt = 0; nt < 4; nt++)
            #pragma unroll
            for (int i = 0; i < 4; i++) acc[mt][nt][i] = 0.f;

    for (int k0 = 0; k0 < K; k0 += BK) {
        // ---- A tile: 128x32 floats = 1024 float4 slots, 4 per thread; split+pack
        #pragma unroll
        for (int l = 0; l < 4; l++) {
            int slot = tid + l * 256;
            int ar  = slot >> 3;      // 0..127
            int ac4 = slot & 7;       // float4 index over k (0..7)
            int grow = rowBase + ar;
            float4 v = make_float4(0.f, 0.f, 0.f, 0.f);
            if (grow < M)
                v = *(const float4*)(A + (size_t)grow * K + k0 + ac4 * 4);
            if (scale) {
                int kc = k0 + ac4 * 4;
                v.x = fmaxf(0.f, fmaf(v.x, scale[kc + 0], shift[kc + 0]));
                v.y = fmaxf(0.f, fmaf(v.y, scale[kc + 1], shift[kc + 1]));
                v.z = fmaxf(0.f, fmaf(v.z, scale[kc + 2], shift[kc + 2]));
                v.w = fmaxf(0.f, fmaf(v.w, scale[kc + 3], shift[kc + 3]));
            }
            int kp = ac4 * 2;
            AsH[ar * AST + kp]     = pack_bf16(v.x, v.y);
            AsH[ar * AST + kp + 1] = pack_bf16(v.z, v.w);
            AsL[ar * AST + kp]     = pack_bf16(v.x - bf_hi_f(v.x), v.y - bf_hi_f(v.y));
            AsL[ar * AST + kp + 1] = pack_bf16(v.z - bf_hi_f(v.z), v.w - bf_hi_f(v.w));
        }
        // ---- B tile: 32x64 floats; pack k-pairs: 16 kp-rows x 16 n4 = 256 slots
        {
            int bkp = tid >> 4;       // 0..15
            int bn4 = tid & 15;       // 0..15 -> n = 4*bn4..+3
            const float* r0p = Bp + (size_t)(k0 + 2 * bkp) * BN + bn4 * 4;
            float4 u0 = *(const float4*)r0p;
            float4 u1 = *(const float4*)(r0p + BN);
            uint32_t* dh = &BsH[bkp * BST + bn4 * 4];
            uint32_t* dl = &BsL[bkp * BST + bn4 * 4];
            dh[0] = pack_bf16(u0.x, u1.x);
            dh[1] = pack_bf16(u0.y, u1.y);
            dh[2] = pack_bf16(u0.z, u1.z);
            dh[3] = pack_bf16(u0.w, u1.w);
            dl[0] = pack_bf16(u0.x - bf_hi_f(u0.x), u1.x - bf_hi_f(u1.x));
            dl[1] = pack_bf16(u0.y - bf_hi_f(u0.y), u1.y - bf_hi_f(u1.y));
            dl[2] = pack_bf16(u0.z - bf_hi_f(u0.z), u1.z - bf_hi_f(u1.z));
            dl[3] = pack_bf16(u0.w - bf_hi_f(u0.w), u1.w - bf_hi_f(u1.w));
        }
        __syncthreads();

        #pragma unroll
        for (int c = 0; c < 2; c++) {       // two k16 chunks per BK=32
            int kpb = c * 8;
            uint32_t ahi[2][4], alo[2][4];
            #pragma unroll
            for (int mt = 0; mt < 2; mt++) {
                int r0 = wm * 32 + mt * 16 + lr;
                ahi[mt][0] = AsH[r0 * AST + kpb + lc];
                ahi[mt][1] = AsH[(r0 + 8) * AST + kpb + lc];
                ahi[mt][2] = AsH[r0 * AST + kpb + lc + 4];
                ahi[mt][3] = AsH[(r0 + 8) * AST + kpb + lc + 4];
                alo[mt][0] = AsL[r0 * AST + kpb + lc];
                alo[mt][1] = AsL[(r0 + 8) * AST + kpb + lc];
                alo[mt][2] = AsL[r0 * AST + kpb + lc + 4];
                alo[mt][3] = AsL[(r0 + 8) * AST + kpb + lc + 4];
            }
            uint32_t bhi[4][2], blo[4][2];
            #pragma unroll
            for (int nt = 0; nt < 4; nt++) {
                int n0 = wn * 32 + nt * 8 + lr;
                bhi[nt][0] = BsH[(kpb + lc) * BST + n0];
                bhi[nt][1] = BsH[(kpb + lc + 4) * BST + n0];
                blo[nt][0] = BsL[(kpb + lc) * BST + n0];
                blo[nt][1] = BsL[(kpb + lc + 4) * BST + n0];
            }
            #pragma unroll
            for (int mt = 0; mt < 2; mt++)
                #pragma unroll
                for (int nt = 0; nt < 4; nt++) {
                    mma_bf16(acc[mt][nt], ahi[mt], bhi[nt]);
                    mma_bf16(acc[mt][nt], ahi[mt], blo[nt]);
                    mma_bf16(acc[mt][nt], alo[mt], bhi[nt]);
                }
        }
        __syncthreads();
    }

    bool dodup = (dup != nullptr) && (p == 0);
    #pragma unroll
    for (int mt = 0; mt < 2; mt++) {
        #pragma unroll
        for (int nt = 0; nt < 4; nt++) {
            int ncol = wn * 32 + nt * 8 + lc * 2;      // col within the 64-block
            int gcol = p * BN + ncol;                  // col within C
            float bx = 0.f, by = 0.f;
            if (bias) { bx = bias[ncol]; by = bias[ncol + 1]; }
            int r = rowBase + wm * 32 + mt * 16 + lr;
            if (r < M) {
                float2 o; o.x = acc[mt][nt][0] + bx; o.y = acc[mt][nt][1] + by;
                *(float2*)(C + (size_t)r * NC + gcol) = o;
                if (dodup) *(float2*)(dup + (size_t)r * C1 + gcol) = o;
            }
            if (r + 8 < M) {
                float2 o; o.x = acc[mt][nt][2] + bx; o.y = acc[mt][nt][3] + by;
                *(float2*)(C + (size_t)(r + 8) * NC + gcol) = o;
                if (dodup) *(float2*)(dup + (size_t)(r + 8) * C1 + gcol) = o;
            }
        }
    }
}

// ---------------- host launch ----------------
extern "C" void kernel_launch(void* const* d_in, const int* in_sizes, int n_in,
                              void* d_out, int out_size) {
    const float* x   = (const float*)d_in[0];
    const void*  ei  = d_in[1];
    const float* W1  = (const float*)d_in[2];
    // d_in[3] = B1 (absorbed by BatchNorm)
    const float* g1  = (const float*)d_in[4];
    const float* be1 = (const float*)d_in[5];
    const float* W2  = (const float*)d_in[6];
    // d_in[7] = B2 (absorbed by BatchNorm)
    const float* g2  = (const float*)d_in[8];
    const float* be2 = (const float*)d_in[9];
    const float* Wfc = (const float*)d_in[10];
    const float* bfc = (const float*)d_in[11];
    float* out = (float*)d_out;

    float *Z, *Hpre, *H2, *T, *Sc, *Sh, *Su, *Sq;
    int *Cnt;
    cudaGetSymbolAddress((void**)&Z,    g_Z);
    cudaGetSymbolAddress((void**)&Hpre, g_Hpre);
    cudaGetSymbolAddress((void**)&H2,   g_H2);
    cudaGetSymbolAddress((void**)&T,    g_T);
    cudaGetSymbolAddress((void**)&Sc,   g_scale);
    cudaGetSymbolAddress((void**)&Sh,   g_shift);
    cudaGetSymbolAddress((void**)&Su,   g_sum);
    cudaGetSymbolAddress((void**)&Sq,   g_sq);
    cudaGetSymbolAddress((void**)&Cnt,  g_cnt);

    const int TB = 256;
    const int nBlkN  = (NN + TB - 1) / TB;
    const int nBlkE  = (EE + TB - 1) / TB;
    const int nBlkSp = (NN + 7) / 8;
    const dim3 gemmG((NN + BM - 1) / BM, 3);
    const dim3 gemmO((NN + BM - 1) / BM, 1);

    // preprocessing
    k_detect<<<1, 32>>>((const long long*)ei);
    cudaMemsetAsync(Cnt, 0, NN * sizeof(int));
    k_count<<<nBlkE, TB>>>(ei);
    k_bsum<<<SCAN_B, 256>>>();
    k_scan_bsum<<<1, 256>>>();
    k_scan_final<<<SCAN_B, 256>>>();
    k_dinv<<<nBlkN, TB>>>();
    k_fill<<<nBlkE, TB>>>(ei);

    // ---- layer 1:  A=x  C=Z  dup=Hpre ----
    tgemm<<<gemmG, TB>>>(x, W1, Z, NN, FIN, C1, nullptr, nullptr, nullptr, Hpre);
    spmm128<<<nBlkSp, TB>>>(Z, Hpre, T);
    spmm64<<<nBlkSp, TB>>>(T, HIDD, Hpre + 2 * HIDD, C1);
    cudaMemsetAsync(Su, 0, C1 * sizeof(float));
    cudaMemsetAsync(Sq, 0, C1 * sizeof(float));
    bn_stats<<<512, C1>>>(Hpre);
    bn_final<<<1, C1>>>(g1, be1);

    // ---- layer 2:  A=Hpre  C=Z  dup=H2 (no aliasing with A) ----
    tgemm<<<gemmG, TB>>>(Hpre, W2, Z, NN, C1, C1, nullptr, Sc, Sh, H2);
    spmm128<<<nBlkSp, TB>>>(Z, H2, T);
    spmm64<<<nBlkSp, TB>>>(T, HIDD, H2 + 2 * HIDD, C1);
    cudaMemsetAsync(Su, 0, C1 * sizeof(float));
    cudaMemsetAsync(Sq, 0, C1 * sizeof(float));
    bn_stats<<<512, C1>>>(H2);
    bn_final<<<1, C1>>>(g2, be2);

    // ---- final fc:  A=H2 -> out ----
    tgemm<<<gemmO, TB>>>(H2, Wfc, out, NN, C1, HIDD, bfc, Sc, Sh, nullptr);

    (void)in_sizes; (void)n_in; (void)out_size;
}

// round 8
// speedup vs baseline: 1.5697x; 1.0695x over previous
#include <cuda_runtime.h>
#include <cuda_bf16.h>
#include <cuda_fp16.h>
#include <cstdint>

#define NN   50000
#define EE   800000
#define FIN  128
#define HIDD 64
#define C1   192          // P*HID
#define EPSB 1e-5f
#define SCAN_B 196        // ceil(NN/256)

// ---------------- static device scratch (no allocations allowed) ----------------
__device__ int g_is64;
__device__ __align__(256) __half g_Zh [(size_t)NN * 128];   // fp16 cols 64..191 of layer GEMM out
__device__ __align__(256) __half g_Th [(size_t)NN * HIDD];  // fp16 hop-1 intermediate
__device__ __align__(256) float g_Hpre[(size_t)NN * C1];
__device__ __align__(256) float g_H2  [(size_t)NN * C1];
__device__ int   g_cnt[NN];
__device__ int   g_rowptr[NN + 1];
__device__ int   g_pos[NN];
__device__ int   g_bsum[SCAN_B];
__device__ __align__(256) int   g_col[EE];
__device__ __align__(256) float g_w  [EE];
__device__ float g_dinv[NN];
__device__ float g_sum[C1];
__device__ float g_sq [C1];
__device__ float g_scale[C1];
__device__ float g_shift[C1];

// ---------------- edge index accessor (dtype-agnostic) ----------------
__device__ __forceinline__ int edge_at(const void* p, long long i) {
    if (g_is64) return (int)((const long long*)p)[i];
    return ((const int*)p)[i];
}

__global__ void k_detect(const long long* e) {
    int lane = threadIdx.x;
    int bad = 0;
    #pragma unroll
    for (int l = 0; l < 2; l++) {
        long long v = e[lane + 32 * l];
        bad |= (v < 0 || v >= NN);
    }
    unsigned m = __ballot_sync(0xffffffffu, bad);
    if (lane == 0) g_is64 = (m == 0u);
}

// ---------------- graph preprocessing ----------------
__global__ void k_count(const void* e) {
    int i = blockIdx.x * blockDim.x + threadIdx.x;
    if (i < EE) {
        int d = edge_at(e, (long long)EE + i);
        atomicAdd(&g_cnt[d], 1);
    }
}

__global__ void k_bsum() {
    __shared__ int sh[256];
    int i = blockIdx.x * 256 + threadIdx.x;
    sh[threadIdx.x] = (i < NN) ? g_cnt[i] : 0;
    __syncthreads();
    for (int s = 128; s > 0; s >>= 1) {
        if (threadIdx.x < s) sh[threadIdx.x] += sh[threadIdx.x + s];
        __syncthreads();
    }
    if (threadIdx.x == 0) g_bsum[blockIdx.x] = sh[0];
}

__global__ void k_scan_bsum() {
    __shared__ int sh[256];
    int t = threadIdx.x;
    int v = (t < SCAN_B) ? g_bsum[t] : 0;
    sh[t] = v;
    __syncthreads();
    for (int off = 1; off < 256; off <<= 1) {
        int tv = (t >= off) ? sh[t - off] : 0;
        __syncthreads();
        sh[t] += tv;
        __syncthreads();
    }
    if (t < SCAN_B) g_bsum[t] = sh[t] - v;
    if (t == 255) g_rowptr[NN] = sh[255];
}

__global__ void k_scan_final() {
    __shared__ int sh[256];
    int t = threadIdx.x;
    int i = blockIdx.x * 256 + t;
    int v = (i < NN) ? g_cnt[i] : 0;
    sh[t] = v;
    __syncthreads();
    for (int off = 1; off < 256; off <<= 1) {
        int tv = (t >= off) ? sh[t - off] : 0;
        __syncthreads();
        sh[t] += tv;
        __syncthreads();
    }
    int excl = sh[t] - v + g_bsum[blockIdx.x];
    if (i < NN) {
        g_rowptr[i] = excl;
        g_pos[i]    = excl;
        g_dinv[i]   = rsqrtf((float)v + 1.0f);   // +1 self loop
    }
}

__global__ void k_fill(const void* e) {
    int i = blockIdx.x * blockDim.x + threadIdx.x;
    if (i < EE) {
        int s = edge_at(e, i);
        int d = edge_at(e, (long long)EE + i);
        int p = atomicAdd(&g_pos[d], 1);
        g_col[p] = s;
        g_w[p]   = g_dinv[s] * g_dinv[d];
    }
}

// ------- hop 1: gather fp16 Zh rows; power-1 -> H fp32, A*z2 -> Th fp16 --------
__global__ __launch_bounds__(256) void spmm128h(
    const __half* __restrict__ Zh, float* __restrict__ H, __half* __restrict__ Th)
{
    int warp = (blockIdx.x * blockDim.x + threadIdx.x) >> 5;
    int lane = threadIdx.x & 31;
    if (warp >= NN) return;
    float dv = g_dinv[warp];
    float ws = dv * dv;
    uint2 zp = ((const uint2*)(Zh + (size_t)warp * 128))[lane];     // 4 halves
    float2 z0 = __half22float2(*(const __half2*)&zp.x);
    float2 z1 = __half22float2(*(const __half2*)&zp.y);
    float a0 = ws * z0.x, a1 = ws * z0.y, a2 = ws * z1.x, a3 = ws * z1.y;
    int e0 = g_rowptr[warp], e1 = g_rowptr[warp + 1];
    #pragma unroll 4
    for (int e = e0; e < e1; e++) {
        int c    = __ldg(&g_col[e]);
        float wt = __ldg(&g_w[e]);
        uint2 vp = ((const uint2*)(Zh + (size_t)c * 128))[lane];
        float2 v0 = __half22float2(*(const __half2*)&vp.x);
        float2 v1 = __half22float2(*(const __half2*)&vp.y);
        a0 = fmaf(wt, v0.x, a0);
        a1 = fmaf(wt, v0.y, a1);
        a2 = fmaf(wt, v1.x, a2);
        a3 = fmaf(wt, v1.y, a3);
    }
    if (lane < 16) {
        float4 o; o.x = a0; o.y = a1; o.z = a2; o.w = a3;
        *(float4*)(H + (size_t)warp * C1 + HIDD + lane * 4) = o;
    } else {
        uint2 op;
        *(__half2*)&op.x = __floats2half2_rn(a0, a1);
        *(__half2*)&op.y = __floats2half2_rn(a2, a3);
        *(uint2*)(Th + (size_t)warp * HIDD + (lane - 16) * 4) = op;
    }
}

// ------- hop 2: gather fp16 Th rows; power-2 -> H fp32 --------------------------
__global__ __launch_bounds__(256) void spmm64h(
    const __half* __restrict__ Th, float* __restrict__ H)
{
    int warp = (blockIdx.x * blockDim.x + threadIdx.x) >> 5;
    int lane = threadIdx.x & 31;
    if (warp >= NN) return;
    float dv = g_dinv[warp];
    float ws = dv * dv;
    uint32_t zp = ((const uint32_t*)(Th + (size_t)warp * HIDD))[lane];
    float2 z = __half22float2(*(const __half2*)&zp);
    float ax = ws * z.x, ay = ws * z.y;
    int e0 = g_rowptr[warp], e1 = g_rowptr[warp + 1];
    #pragma unroll 4
    for (int e = e0; e < e1; e++) {
        int c    = __ldg(&g_col[e]);
        float wt = __ldg(&g_w[e]);
        uint32_t vp = ((const uint32_t*)(Th + (size_t)c * HIDD))[lane];
        float2 v = __half22float2(*(const __half2*)&vp);
        ax = fmaf(wt, v.x, ax);
        ay = fmaf(wt, v.y, ay);
    }
    float2 o; o.x = ax; o.y = ay;
    *(float2*)(H + (size_t)warp * C1 + 2 * HIDD + lane * 2) = o;
}

// ---------------- BatchNorm stats ----------------
__global__ void bn_stats(const float* __restrict__ H) {
    int c = threadIdx.x;
    float s = 0.f, q = 0.f;
    for (int r = blockIdx.x; r < NN; r += gridDim.x) {
        float v = H[(size_t)r * C1 + c];
        s += v;
        q = fmaf(v, v, q);
    }
    atomicAdd(&g_sum[c], s);
    atomicAdd(&g_sq[c], q);
}

__global__ void bn_final(const float* __restrict__ g, const float* __restrict__ be) {
    int c = threadIdx.x;
    if (c < C1) {
        float mu  = g_sum[c] * (1.0f / NN);
        float var = g_sq[c] * (1.0f / NN) - mu * mu;
        float inv = rsqrtf(var + EPSB);
        float sc  = inv * g[c];
        g_scale[c] = sc;
        g_shift[c] = be[c] - mu * sc;
    }
}

// ------------- bf16 split-2 tensor-core GEMM (m16n8k16, 3-term compensation) ----
// out = act(A)[M,K] @ W[p][K,64] (+bias),  act = BN+ReLU if scale given
// p==0 -> fp32 store into dup (ld C1); p>=1 -> fp16 store into duph (ld 128);
// C (ld NC) stored only if non-null (final FC).
#define BM 128
#define BN 64
#define BK 32
#define KP 16
#define AST 20
#define BST 72

__device__ __forceinline__ uint32_t pack_bf16(float x, float y) {
    __nv_bfloat162 t;
    t.x = __float2bfloat16_rn(x);
    t.y = __float2bfloat16_rn(y);
    return *reinterpret_cast<uint32_t*>(&t);
}
__device__ __forceinline__ float bf_hi_f(float x) {
    return __bfloat162float(__float2bfloat16_rn(x));
}

__device__ __forceinline__ void mma_bf16(float* d, const uint32_t* a, const uint32_t* b) {
    asm volatile(
        "mma.sync.aligned.m16n8k16.row.col.f32.bf16.bf16.f32 "
        "{%0,%1,%2,%3},{%4,%5,%6,%7},{%8,%9},{%0,%1,%2,%3};\n"
        : "+f"(d[0]), "+f"(d[1]), "+f"(d[2]), "+f"(d[3])
        : "r"(a[0]), "r"(a[1]), "r"(a[2]), "r"(a[3]), "r"(b[0]), "r"(b[1]));
}

__global__ __launch_bounds__(256, 2) void tgemm(
    const float* __restrict__ A, const float* __restrict__ Bmat,
    float* __restrict__ C, int M, int K, int NC,
    const float* __restrict__ bias,
    const float* __restrict__ scale, const float* __restrict__ shift,
    float* __restrict__ dup, __half* __restrict__ duph)
{
    __shared__ uint32_t AsH[BM * AST];
    __shared__ uint32_t AsL[BM * AST];
    __shared__ uint32_t BsH[KP * BST];
    __shared__ uint32_t BsL[KP * BST];
    int p = blockIdx.y;
    const float* Bp = Bmat + (size_t)p * K * BN;
    int rowBase = blockIdx.x * BM;
    int tid  = threadIdx.x;
    int lane = tid & 31;
    int w    = tid >> 5;
    int wm   = w & 3;
    int wn   = w >> 2;
    int lr   = lane >> 2;
    int lc   = lane & 3;

    float acc[2][4][4];
    #pragma unroll
    for (int mt = 0; mt < 2; mt++)
        #pragma unroll
        for (int nt = 0; nt < 4; nt++)
            #pragma unroll
            for (int i = 0; i < 4; i++) acc[mt][nt][i] = 0.f;

    for (int k0 = 0; k0 < K; k0 += BK) {
        #pragma unroll
        for (int l = 0; l < 4; l++) {
            int slot = tid + l * 256;
            int ar  = slot >> 3;
            int ac4 = slot & 7;
            int grow = rowBase + ar;
            float4 v = make_float4(0.f, 0.f, 0.f, 0.f);
            if (grow < M)
                v = *(const float4*)(A + (size_t)grow * K + k0 + ac4 * 4);
            if (scale) {
                int kc = k0 + ac4 * 4;
                v.x = fmaxf(0.f, fmaf(v.x, scale[kc + 0], shift[kc + 0]));
                v.y = fmaxf(0.f, fmaf(v.y, scale[kc + 1], shift[kc + 1]));
                v.z = fmaxf(0.f, fmaf(v.z, scale[kc + 2], shift[kc + 2]));
                v.w = fmaxf(0.f, fmaf(v.w, scale[kc + 3], shift[kc + 3]));
            }
            int kp = ac4 * 2;
            AsH[ar * AST + kp]     = pack_bf16(v.x, v.y);
            AsH[ar * AST + kp + 1] = pack_bf16(v.z, v.w);
            AsL[ar * AST + kp]     = pack_bf16(v.x - bf_hi_f(v.x), v.y - bf_hi_f(v.y));
            AsL[ar * AST + kp + 1] = pack_bf16(v.z - bf_hi_f(v.z), v.w - bf_hi_f(v.w));
        }
        {
            int bkp = tid >> 4;
            int bn4 = tid & 15;
            const float* r0p = Bp + (size_t)(k0 + 2 * bkp) * BN + bn4 * 4;
            float4 u0 = *(const float4*)r0p;
            float4 u1 = *(const float4*)(r0p + BN);
            uint32_t* dh = &BsH[bkp * BST + bn4 * 4];
            uint32_t* dl = &BsL[bkp * BST + bn4 * 4];
            dh[0] = pack_bf16(u0.x, u1.x);
            dh[1] = pack_bf16(u0.y, u1.y);
            dh[2] = pack_bf16(u0.z, u1.z);
            dh[3] = pack_bf16(u0.w, u1.w);
            dl[0] = pack_bf16(u0.x - bf_hi_f(u0.x), u1.x - bf_hi_f(u1.x));
            dl[1] = pack_bf16(u0.y - bf_hi_f(u0.y), u1.y - bf_hi_f(u1.y));
            dl[2] = pack_bf16(u0.z - bf_hi_f(u0.z), u1.z - bf_hi_f(u1.z));
            dl[3] = pack_bf16(u0.w - bf_hi_f(u0.w), u1.w - bf_hi_f(u1.w));
        }
        __syncthreads();

        #pragma unroll
        for (int c = 0; c < 2; c++) {
            int kpb = c * 8;
            uint32_t ahi[2][4], alo[2][4];
            #pragma unroll
            for (int mt = 0; mt < 2; mt++) {
                int r0 = wm * 32 + mt * 16 + lr;
                ahi[mt][0] = AsH[r0 * AST + kpb + lc];
                ahi[mt][1] = AsH[(r0 + 8) * AST + kpb + lc];
                ahi[mt][2] = AsH[r0 * AST + kpb + lc + 4];
                ahi[mt][3] = AsH[(r0 + 8) * AST + kpb + lc + 4];
                alo[mt][0] = AsL[r0 * AST + kpb + lc];
                alo[mt][1] = AsL[(r0 + 8) * AST + kpb + lc];
                alo[mt][2] = AsL[r0 * AST + kpb + lc + 4];
                alo[mt][3] = AsL[(r0 + 8) * AST + kpb + lc + 4];
            }
            uint32_t bhi[4][2], blo[4][2];
            #pragma unroll
            for (int nt = 0; nt < 4; nt++) {
                int n0 = wn * 32 + nt * 8 + lr;
                bhi[nt][0] = BsH[(kpb + lc) * BST + n0];
                bhi[nt][1] = BsH[(kpb + lc + 4) * BST + n0];
                blo[nt][0] = BsL[(kpb + lc) * BST + n0];
                blo[nt][1] = BsL[(kpb + lc + 4) * BST + n0];
            }
            #pragma unroll
            for (int mt = 0; mt < 2; mt++)
                #pragma unroll
                for (int nt = 0; nt < 4; nt++) {
                    mma_bf16(acc[mt][nt], ahi[mt], bhi[nt]);
                    mma_bf16(acc[mt][nt], ahi[mt], blo[nt]);
                    mma_bf16(acc[mt][nt], alo[mt], bhi[nt]);
                }
        }
        __syncthreads();
    }

    #pragma unroll
    for (int mt = 0; mt < 2; mt++) {
        #pragma unroll
        for (int nt = 0; nt < 4; nt++) {
            int ncol = wn * 32 + nt * 8 + lc * 2;
            int gcol = p * BN + ncol;
            float bx = 0.f, by = 0.f;
            if (bias) { bx = bias[ncol]; by = bias[ncol + 1]; }
            #pragma unroll
            for (int hh = 0; hh < 2; hh++) {
                int r = rowBase + wm * 32 + mt * 16 + lr + hh * 8;
                if (r < M) {
                    float ox = acc[mt][nt][2 * hh]     + bx;
                    float oy = acc[mt][nt][2 * hh + 1] + by;
                    if (C) {
                        float2 o; o.x = ox; o.y = oy;
                        *(float2*)(C + (size_t)r * NC + gcol) = o;
                    }
                    if (p == 0) {
                        if (dup) {
                            float2 o; o.x = ox; o.y = oy;
                            *(float2*)(dup + (size_t)r * C1 + gcol) = o;
                        }
                    } else if (duph) {
                        __half2 h = __floats2half2_rn(ox, oy);
                        *(__half2*)(duph + (size_t)r * 128 + (gcol - BN)) = h;
                    }
                }
            }
        }
    }
}

// ---------------- host launch ----------------
extern "C" void kernel_launch(void* const* d_in, const int* in_sizes, int n_in,
                              void* d_out, int out_size) {
    const float* x   = (const float*)d_in[0];
    const void*  ei  = d_in[1];
    const float* W1  = (const float*)d_in[2];
    // d_in[3] = B1 (absorbed by BatchNorm)
    const float* g1  = (const float*)d_in[4];
    const float* be1 = (const float*)d_in[5];
    const float* W2  = (const float*)d_in[6];
    // d_in[7] = B2 (absorbed by BatchNorm)
    const float* g2  = (const float*)d_in[8];
    const float* be2 = (const float*)d_in[9];
    const float* Wfc = (const float*)d_in[10];
    const float* bfc = (const float*)d_in[11];
    float* out = (float*)d_out;

    float *Hpre, *H2, *Sc, *Sh, *Su, *Sq;
    __half *Zh, *Th;
    int *Cnt;
    cudaGetSymbolAddress((void**)&Zh,   g_Zh);
    cudaGetSymbolAddress((void**)&Th,   g_Th);
    cudaGetSymbolAddress((void**)&Hpre, g_Hpre);
    cudaGetSymbolAddress((void**)&H2,   g_H2);
    cudaGetSymbolAddress((void**)&Sc,   g_scale);
    cudaGetSymbolAddress((void**)&Sh,   g_shift);
    cudaGetSymbolAddress((void**)&Su,   g_sum);
    cudaGetSymbolAddress((void**)&Sq,   g_sq);
    cudaGetSymbolAddress((void**)&Cnt,  g_cnt);

    const int TB = 256;
    const int nBlkE  = (EE + TB - 1) / TB;
    const int nBlkSp = (NN + 7) / 8;
    const dim3 gemmG((NN + BM - 1) / BM, 3);
    const dim3 gemmO((NN + BM - 1) / BM, 1);

    // preprocessing
    k_detect<<<1, 32>>>((const long long*)ei);
    cudaMemsetAsync(Cnt, 0, NN * sizeof(int));
    k_count<<<nBlkE, TB>>>(ei);
    k_bsum<<<SCAN_B, 256>>>();
    k_scan_bsum<<<1, 256>>>();
    k_scan_final<<<SCAN_B, 256>>>();
    k_fill<<<nBlkE, TB>>>(ei);

    // ---- layer 1:  power0 -> Hpre (fp32), powers 1,2 staged via Zh/Th fp16 ----
    tgemm<<<gemmG, TB>>>(x, W1, nullptr, NN, FIN, C1, nullptr, nullptr, nullptr, Hpre, Zh);
    spmm128h<<<nBlkSp, TB>>>(Zh, Hpre, Th);
    spmm64h<<<nBlkSp, TB>>>(Th, Hpre);
    cudaMemsetAsync(Su, 0, C1 * sizeof(float));
    cudaMemsetAsync(Sq, 0, C1 * sizeof(float));
    bn_stats<<<512, C1>>>(Hpre);
    bn_final<<<1, C1>>>(g1, be1);

    // ---- layer 2 (BN1+ReLU fused into A load) ----
    tgemm<<<gemmG, TB>>>(Hpre, W2, nullptr, NN, C1, C1, nullptr, Sc, Sh, H2, Zh);
    spmm128h<<<nBlkSp, TB>>>(Zh, H2, Th);
    spmm64h<<<nBlkSp, TB>>>(Th, H2);
    cudaMemsetAsync(Su, 0, C1 * sizeof(float));
    cudaMemsetAsync(Sq, 0, C1 * sizeof(float));
    bn_stats<<<512, C1>>>(H2);
    bn_final<<<1, C1>>>(g2, be2);

    // ---- final fc (BN2+ReLU fused into A load) ----
    tgemm<<<gemmO, TB>>>(H2, Wfc, out, NN, C1, HIDD, bfc, Sc, Sh, nullptr, nullptr);

    (void)in_sizes; (void)n_in; (void)out_size;
}

// round 9
// speedup vs baseline: 1.6430x; 1.0467x over previous
#include <cuda_runtime.h>
#include <cuda_bf16.h>
#include <cuda_fp16.h>
#include <cstdint>

#define NN   50000
#define EE   800000
#define FIN  128
#define HIDD 64
#define C1   192          // P*HID
#define EPSB 1e-5f
#define SCAN_B 196        // ceil(NN/256)

// ---------------- static device scratch (no allocations allowed) ----------------
__device__ int g_is64;
__device__ __align__(256) __half g_Zh [(size_t)NN * 128];   // fp16 cols 64..191 of layer GEMM out
__device__ __align__(256) __half g_Th [(size_t)NN * HIDD];  // fp16 hop-1 intermediate
__device__ __align__(256) float g_Hpre[(size_t)NN * C1];
__device__ __align__(256) float g_H2  [(size_t)NN * C1];
__device__ int   g_cnt[NN];
__device__ int   g_rowptr[NN + 1];
__device__ int   g_pos[NN];
__device__ int   g_bsum[SCAN_B];
__device__ __align__(256) int   g_col[EE];
__device__ __align__(256) float g_w  [EE];
__device__ float g_dinv[NN];
__device__ __align__(256) float g_stats[2 * C1];   // [0..C1) sums, [C1..2C1) sumsq

// ---------------- edge index accessor (dtype-agnostic) ----------------
__device__ __forceinline__ int edge_at(const void* p, long long i) {
    if (g_is64) return (int)((const long long*)p)[i];
    return ((const int*)p)[i];
}

__global__ void k_detect(const long long* e) {
    int lane = threadIdx.x;
    int bad = 0;
    #pragma unroll
    for (int l = 0; l < 2; l++) {
        long long v = e[lane + 32 * l];
        bad |= (v < 0 || v >= NN);
    }
    unsigned m = __ballot_sync(0xffffffffu, bad);
    if (lane == 0) g_is64 = (m == 0u);
}

// ---------------- graph preprocessing ----------------
__global__ void k_count(const void* e) {
    int i = blockIdx.x * blockDim.x + threadIdx.x;
    if (i < EE) {
        int d = edge_at(e, (long long)EE + i);
        atomicAdd(&g_cnt[d], 1);
    }
}

__global__ void k_bsum() {
    __shared__ int sh[256];
    int i = blockIdx.x * 256 + threadIdx.x;
    sh[threadIdx.x] = (i < NN) ? g_cnt[i] : 0;
    __syncthreads();
    for (int s = 128; s > 0; s >>= 1) {
        if (threadIdx.x < s) sh[threadIdx.x] += sh[threadIdx.x + s];
        __syncthreads();
    }
    if (threadIdx.x == 0) g_bsum[blockIdx.x] = sh[0];
}

__global__ void k_scan_bsum() {
    __shared__ int sh[256];
    int t = threadIdx.x;
    int v = (t < SCAN_B) ? g_bsum[t] : 0;
    sh[t] = v;
    __syncthreads();
    for (int off = 1; off < 256; off <<= 1) {
        int tv = (t >= off) ? sh[t - off] : 0;
        __syncthreads();
        sh[t] += tv;
        __syncthreads();
    }
    if (t < SCAN_B) g_bsum[t] = sh[t] - v;
    if (t == 255) g_rowptr[NN] = sh[255];
}

__global__ void k_scan_final() {
    __shared__ int sh[256];
    int t = threadIdx.x;
    int i = blockIdx.x * 256 + t;
    int v = (i < NN) ? g_cnt[i] : 0;
    sh[t] = v;
    __syncthreads();
    for (int off = 1; off < 256; off <<= 1) {
        int tv = (t >= off) ? sh[t - off] : 0;
        __syncthreads();
        sh[t] += tv;
        __syncthreads();
    }
    int excl = sh[t] - v + g_bsum[blockIdx.x];
    if (i < NN) {
        g_rowptr[i] = excl;
        g_pos[i]    = excl;
        g_dinv[i]   = rsqrtf((float)v + 1.0f);   // +1 self loop
    }
}

__global__ void k_fill(const void* e) {
    int i = blockIdx.x * blockDim.x + threadIdx.x;
    if (i < EE) {
        int s = edge_at(e, i);
        int d = edge_at(e, (long long)EE + i);
        int p = atomicAdd(&g_pos[d], 1);
        g_col[p] = s;
        g_w[p]   = g_dinv[s] * g_dinv[d];
    }
}

// ------- hop 1: gather fp16 Zh rows; power-1 -> H fp32, A*z2 -> Th fp16 --------
__global__ __launch_bounds__(256) void spmm128h(
    const __half* __restrict__ Zh, float* __restrict__ H, __half* __restrict__ Th)
{
    int warp = (blockIdx.x * blockDim.x + threadIdx.x) >> 5;
    int lane = threadIdx.x & 31;
    if (warp >= NN) return;
    float dv = g_dinv[warp];
    float ws = dv * dv;
    uint2 zp = ((const uint2*)(Zh + (size_t)warp * 128))[lane];     // 4 halves
    float2 z0 = __half22float2(*(const __half2*)&zp.x);
    float2 z1 = __half22float2(*(const __half2*)&zp.y);
    float a0 = ws * z0.x, a1 = ws * z0.y, a2 = ws * z1.x, a3 = ws * z1.y;
    int e0 = g_rowptr[warp], e1 = g_rowptr[warp + 1];
    #pragma unroll 4
    for (int e = e0; e < e1; e++) {
        int c    = __ldg(&g_col[e]);
        float wt = __ldg(&g_w[e]);
        uint2 vp = ((const uint2*)(Zh + (size_t)c * 128))[lane];
        float2 v0 = __half22float2(*(const __half2*)&vp.x);
        float2 v1 = __half22float2(*(const __half2*)&vp.y);
        a0 = fmaf(wt, v0.x, a0);
        a1 = fmaf(wt, v0.y, a1);
        a2 = fmaf(wt, v1.x, a2);
        a3 = fmaf(wt, v1.y, a3);
    }
    if (lane < 16) {
        float4 o; o.x = a0; o.y = a1; o.z = a2; o.w = a3;
        *(float4*)(H + (size_t)warp * C1 + HIDD + lane * 4) = o;
    } else {
        uint2 op;
        *(__half2*)&op.x = __floats2half2_rn(a0, a1);
        *(__half2*)&op.y = __floats2half2_rn(a2, a3);
        *(uint2*)(Th + (size_t)warp * HIDD + (lane - 16) * 4) = op;
    }
}

// ------- hop 2: gather fp16 Th rows; power-2 -> H fp32 --------------------------
__global__ __launch_bounds__(256) void spmm64h(
    const __half* __restrict__ Th, float* __restrict__ H)
{
    int warp = (blockIdx.x * blockDim.x + threadIdx.x) >> 5;
    int lane = threadIdx.x & 31;
    if (warp >= NN) return;
    float dv = g_dinv[warp];
    float ws = dv * dv;
    uint32_t zp = ((const uint32_t*)(Th + (size_t)warp * HIDD))[lane];
    float2 z = __half22float2(*(const __half2*)&zp);
    float ax = ws * z.x, ay = ws * z.y;
    int e0 = g_rowptr[warp], e1 = g_rowptr[warp + 1];
    #pragma unroll 4
    for (int e = e0; e < e1; e++) {
        int c    = __ldg(&g_col[e]);
        float wt = __ldg(&g_w[e]);
        uint32_t vp = ((const uint32_t*)(Th + (size_t)c * HIDD))[lane];
        float2 v = __half22float2(*(const __half2*)&vp);
        ax = fmaf(wt, v.x, ax);
        ay = fmaf(wt, v.y, ay);
    }
    float2 o; o.x = ax; o.y = ay;
    *(float2*)(H + (size_t)warp * C1 + 2 * HIDD + lane * 2) = o;
}

// ---------------- BatchNorm stats (sum+sumsq into g_stats) ----------------
__global__ void bn_stats(const float* __restrict__ H) {
    int c = threadIdx.x;
    float s = 0.f, q = 0.f;
    for (int r = blockIdx.x; r < NN; r += gridDim.x) {
        float v = H[(size_t)r * C1 + c];
        s += v;
        q = fmaf(v, v, q);
    }
    atomicAdd(&g_stats[c], s);
    atomicAdd(&g_stats[C1 + c], q);
}

// ------------- bf16 split-2 tensor-core GEMM (m16n8k16, 3-term compensation) ----
// out = act(A)[M,K] @ W[p][K,64] (+bias); act = BN+ReLU computed from g_stats
// when gvec != null (scale/shift derived per block in the prologue).
// p==0 -> fp32 store into dup (ld C1); p>=1 -> fp16 store into duph (ld 128);
// C (ld NC) stored only if non-null (final FC).
#define BM 128
#define BN 64
#define BK 32
#define KP 16
#define AST 20
#define BST 72

__device__ __forceinline__ uint32_t pack_bf16(float x, float y) {
    __nv_bfloat162 t;
    t.x = __float2bfloat16_rn(x);
    t.y = __float2bfloat16_rn(y);
    return *reinterpret_cast<uint32_t*>(&t);
}
__device__ __forceinline__ float bf_hi_f(float x) {
    return __bfloat162float(__float2bfloat16_rn(x));
}

__device__ __forceinline__ void mma_bf16(float* d, const uint32_t* a, const uint32_t* b) {
    asm volatile(
        "mma.sync.aligned.m16n8k16.row.col.f32.bf16.bf16.f32 "
        "{%0,%1,%2,%3},{%4,%5,%6,%7},{%8,%9},{%0,%1,%2,%3};\n"
        : "+f"(d[0]), "+f"(d[1]), "+f"(d[2]), "+f"(d[3])
        : "r"(a[0]), "r"(a[1]), "r"(a[2]), "r"(a[3]), "r"(b[0]), "r"(b[1]));
}

__global__ __launch_bounds__(256, 2) void tgemm(
    const float* __restrict__ A, const float* __restrict__ Bmat,
    float* __restrict__ C, int M, int K, int NC,
    const float* __restrict__ bias,
    const float* __restrict__ gvec, const float* __restrict__ bevec,
    float* __restrict__ dup, __half* __restrict__ duph)
{
    __shared__ uint32_t AsH[BM * AST];
    __shared__ uint32_t AsL[BM * AST];
    __shared__ uint32_t BsH[KP * BST];
    __shared__ uint32_t BsL[KP * BST];
    __shared__ float sSc[C1];
    __shared__ float sSh[C1];
    int p = blockIdx.y;
    const float* Bp = Bmat + (size_t)p * K * BN;
    int rowBase = blockIdx.x * BM;
    int tid  = threadIdx.x;
    int lane = tid & 31;
    int w    = tid >> 5;
    int wm   = w & 3;
    int wn   = w >> 2;
    int lr   = lane >> 2;
    int lc   = lane & 3;

    bool hasbn = (gvec != nullptr);
    if (hasbn) {
        if (tid < C1) {
            float mu  = g_stats[tid] * (1.0f / NN);
            float var = g_stats[C1 + tid] * (1.0f / NN) - mu * mu;
            float inv = rsqrtf(var + EPSB);
            float sc  = inv * gvec[tid];
            sSc[tid] = sc;
            sSh[tid] = bevec[tid] - mu * sc;
        }
        __syncthreads();
    }

    float acc[2][4][4];
    #pragma unroll
    for (int mt = 0; mt < 2; mt++)
        #pragma unroll
        for (int nt = 0; nt < 4; nt++)
            #pragma unroll
            for (int i = 0; i < 4; i++) acc[mt][nt][i] = 0.f;

    for (int k0 = 0; k0 < K; k0 += BK) {
        #pragma unroll
        for (int l = 0; l < 4; l++) {
            int slot = tid + l * 256;
            int ar  = slot >> 3;
            int ac4 = slot & 7;
            int grow = rowBase + ar;
            float4 v = make_float4(0.f, 0.f, 0.f, 0.f);
            if (grow < M)
                v = *(const float4*)(A + (size_t)grow * K + k0 + ac4 * 4);
            if (hasbn) {
                int kc = k0 + ac4 * 4;
                v.x = fmaxf(0.f, fmaf(v.x, sSc[kc + 0], sSh[kc + 0]));
                v.y = fmaxf(0.f, fmaf(v.y, sSc[kc + 1], sSh[kc + 1]));
                v.z = fmaxf(0.f, fmaf(v.z, sSc[kc + 2], sSh[kc + 2]));
                v.w = fmaxf(0.f, fmaf(v.w, sSc[kc + 3], sSh[kc + 3]));
            }
            int kp = ac4 * 2;
            AsH[ar * AST + kp]     = pack_bf16(v.x, v.y);
            AsH[ar * AST + kp + 1] = pack_bf16(v.z, v.w);
            AsL[ar * AST + kp]     = pack_bf16(v.x - bf_hi_f(v.x), v.y - bf_hi_f(v.y));
            AsL[ar * AST + kp + 1] = pack_bf16(v.z - bf_hi_f(v.z), v.w - bf_hi_f(v.w));
        }
        {
            int bkp = tid >> 4;
            int bn4 = tid & 15;
            const float* r0p = Bp + (size_t)(k0 + 2 * bkp) * BN + bn4 * 4;
            float4 u0 = *(const float4*)r0p;
            float4 u1 = *(const float4*)(r0p + BN);
            uint32_t* dh = &BsH[bkp * BST + bn4 * 4];
            uint32_t* dl = &BsL[bkp * BST + bn4 * 4];
            dh[0] = pack_bf16(u0.x, u1.x);
            dh[1] = pack_bf16(u0.y, u1.y);
            dh[2] = pack_bf16(u0.z, u1.z);
            dh[3] = pack_bf16(u0.w, u1.w);
            dl[0] = pack_bf16(u0.x - bf_hi_f(u0.x), u1.x - bf_hi_f(u1.x));
            dl[1] = pack_bf16(u0.y - bf_hi_f(u0.y), u1.y - bf_hi_f(u1.y));
            dl[2] = pack_bf16(u0.z - bf_hi_f(u0.z), u1.z - bf_hi_f(u1.z));
            dl[3] = pack_bf16(u0.w - bf_hi_f(u0.w), u1.w - bf_hi_f(u1.w));
        }
        __syncthreads();

        #pragma unroll
        for (int c = 0; c < 2; c++) {
            int kpb = c * 8;
            uint32_t ahi[2][4], alo[2][4];
            #pragma unroll
            for (int mt = 0; mt < 2; mt++) {
                int r0 = wm * 32 + mt * 16 + lr;
                ahi[mt][0] = AsH[r0 * AST + kpb + lc];
                ahi[mt][1] = AsH[(r0 + 8) * AST + kpb + lc];
                ahi[mt][2] = AsH[r0 * AST + kpb + lc + 4];
                ahi[mt][3] = AsH[(r0 + 8) * AST + kpb + lc + 4];
                alo[mt][0] = AsL[r0 * AST + kpb + lc];
                alo[mt][1] = AsL[(r0 + 8) * AST + kpb + lc];
                alo[mt][2] = AsL[r0 * AST + kpb + lc + 4];
                alo[mt][3] = AsL[(r0 + 8) * AST + kpb + lc + 4];
            }
            uint32_t bhi[4][2], blo[4][2];
            #pragma unroll
            for (int nt = 0; nt < 4; nt++) {
                int n0 = wn * 32 + nt * 8 + lr;
                bhi[nt][0] = BsH[(kpb + lc) * BST + n0];
                bhi[nt][1] = BsH[(kpb + lc + 4) * BST + n0];
                blo[nt][0] = BsL[(kpb + lc) * BST + n0];
                blo[nt][1] = BsL[(kpb + lc + 4) * BST + n0];
            }
            #pragma unroll
            for (int mt = 0; mt < 2; mt++)
                #pragma unroll
                for (int nt = 0; nt < 4; nt++) {
                    mma_bf16(acc[mt][nt], ahi[mt], bhi[nt]);
                    mma_bf16(acc[mt][nt], ahi[mt], blo[nt]);
                    mma_bf16(acc[mt][nt], alo[mt], bhi[nt]);
                }
        }
        __syncthreads();
    }

    #pragma unroll
    for (int mt = 0; mt < 2; mt++) {
        #pragma unroll
        for (int nt = 0; nt < 4; nt++) {
            int ncol = wn * 32 + nt * 8 + lc * 2;
            int gcol = p * BN + ncol;
            float bx = 0.f, by = 0.f;
            if (bias) { bx = bias[ncol]; by = bias[ncol + 1]; }
            #pragma unroll
            for (int hh = 0; hh < 2; hh++) {
                int r = rowBase + wm * 32 + mt * 16 + lr + hh * 8;
                if (r < M) {
                    float ox = acc[mt][nt][2 * hh]     + bx;
                    float oy = acc[mt][nt][2 * hh + 1] + by;
                    if (C) {
                        float2 o; o.x = ox; o.y = oy;
                        *(float2*)(C + (size_t)r * NC + gcol) = o;
                    }
                    if (p == 0) {
                        if (dup) {
                            float2 o; o.x = ox; o.y = oy;
                            *(float2*)(dup + (size_t)r * C1 + gcol) = o;
                        }
                    } else if (duph) {
                        __half2 h = __floats2half2_rn(ox, oy);
                        *(__half2*)(duph + (size_t)r * 128 + (gcol - BN)) = h;
                    }
                }
            }
        }
    }
}

// ---------------- host launch ----------------
extern "C" void kernel_launch(void* const* d_in, const int* in_sizes, int n_in,
                              void* d_out, int out_size) {
    const float* x   = (const float*)d_in[0];
    const void*  ei  = d_in[1];
    const float* W1  = (const float*)d_in[2];
    // d_in[3] = B1 (absorbed by BatchNorm)
    const float* g1  = (const float*)d_in[4];
    const float* be1 = (const float*)d_in[5];
    const float* W2  = (const float*)d_in[6];
    // d_in[7] = B2 (absorbed by BatchNorm)
    const float* g2  = (const float*)d_in[8];
    const float* be2 = (const float*)d_in[9];
    const float* Wfc = (const float*)d_in[10];
    const float* bfc = (const float*)d_in[11];
    float* out = (float*)d_out;

    float *Hpre, *H2, *St;
    __half *Zh, *Th;
    int *Cnt;
    cudaGetSymbolAddress((void**)&Zh,   g_Zh);
    cudaGetSymbolAddress((void**)&Th,   g_Th);
    cudaGetSymbolAddress((void**)&Hpre, g_Hpre);
    cudaGetSymbolAddress((void**)&H2,   g_H2);
    cudaGetSymbolAddress((void**)&St,   g_stats);
    cudaGetSymbolAddress((void**)&Cnt,  g_cnt);

    // Lazily created host-side resources (identical capture graph every call;
    // no device-memory allocation involved).
    static cudaStream_t sB = nullptr;
    static cudaEvent_t evFork = nullptr, evJoin = nullptr;
    if (!sB) {
        cudaStreamCreateWithFlags(&sB, cudaStreamNonBlocking);
        cudaEventCreateWithFlags(&evFork, cudaEventDisableTiming);
        cudaEventCreateWithFlags(&evJoin, cudaEventDisableTiming);
    }

    const int TB = 256;
    const int nBlkE  = (EE + TB - 1) / TB;
    const int nBlkSp = (NN + 7) / 8;
    const dim3 gemmG((NN + BM - 1) / BM, 3);
    const dim3 gemmO((NN + BM - 1) / BM, 1);

    // ---- fork: CSR preprocessing on side stream, layer-1 GEMM on main --------
    cudaEventRecord(evFork, 0);
    cudaStreamWaitEvent(sB, evFork, 0);

    k_detect<<<1, 32, 0, sB>>>((const long long*)ei);
    cudaMemsetAsync(Cnt, 0, NN * sizeof(int), sB);
    k_count<<<nBlkE, TB, 0, sB>>>(ei);
    k_bsum<<<SCAN_B, 256, 0, sB>>>();
    k_scan_bsum<<<1, 256, 0, sB>>>();
    k_scan_final<<<SCAN_B, 256, 0, sB>>>();
    k_fill<<<nBlkE, TB, 0, sB>>>(ei);
    cudaEventRecord(evJoin, sB);

    // main stream: layer-1 GEMM (independent of graph preprocessing)
    tgemm<<<gemmG, TB>>>(x, W1, nullptr, NN, FIN, C1, nullptr, nullptr, nullptr, Hpre, Zh);
    cudaMemsetAsync(St, 0, 2 * C1 * sizeof(float));   // stats for layer 1

    cudaStreamWaitEvent(0, evJoin, 0);                // join: SpMM needs CSR + Zh

    // ---- layer 1 propagation + stats ----
    spmm128h<<<nBlkSp, TB>>>(Zh, Hpre, Th);
    spmm64h<<<nBlkSp, TB>>>(Th, Hpre);
    bn_stats<<<512, C1>>>(Hpre);

    // ---- layer 2 (BN1+ReLU folded into GEMM prologue from g_stats) ----
    tgemm<<<gemmG, TB>>>(Hpre, W2, nullptr, NN, C1, C1, nullptr, g1, be1, H2, Zh);
    cudaMemsetAsync(St, 0, 2 * C1 * sizeof(float));   // stats for layer 2 (after tgemm read)
    spmm128h<<<nBlkSp, TB>>>(Zh, H2, Th);
    spmm64h<<<nBlkSp, TB>>>(Th, H2);
    bn_stats<<<512, C1>>>(H2);

    // ---- final fc (BN2+ReLU folded into GEMM prologue) ----
    tgemm<<<gemmO, TB>>>(H2, Wfc, out, NN, C1, HIDD, bfc, g2, be2, nullptr, nullptr);

    (void)in_sizes; (void)n_in; (void)out_size;
}

// round 10
// speedup vs baseline: 1.6893x; 1.0282x over previous
#include <cuda_runtime.h>
#include <cuda_bf16.h>
#include <cuda_fp16.h>
#include <cstdint>

#define NN   50000
#define EE   800000
#define FIN  128
#define HIDD 64
#define C1   192          // P*HID
#define EPSB 1e-5f
#define SCAN_B 196        // ceil(NN/256)

// ---------------- static device scratch (no allocations allowed) ----------------
__device__ int g_is64;
__device__ __align__(256) __half g_Zh [(size_t)NN * 128];   // fp16 cols 64..191 of layer GEMM out
__device__ __align__(256) __half g_Th [(size_t)NN * HIDD];  // fp16 hop-1 intermediate
__device__ __align__(256) float g_Hpre[(size_t)NN * C1];
__device__ __align__(256) float g_H2  [(size_t)NN * C1];
__device__ int   g_cnt[NN];
__device__ int   g_rowptr[NN + 1];
__device__ int   g_pos[NN];
__device__ int   g_bsum[SCAN_B];
__device__ __align__(256) int2  g_edge[EE];        // {col, w as float bits}
__device__ float g_dinv[NN];
__device__ __align__(256) float g_stats[2 * C1];   // [0..C1) sums, [C1..2C1) sumsq

// ---------------- edge index accessor (dtype-agnostic) ----------------
__device__ __forceinline__ int edge_at(const void* p, long long i) {
    if (g_is64) return (int)((const long long*)p)[i];
    return ((const int*)p)[i];
}

__global__ void k_detect(const long long* e) {
    int lane = threadIdx.x;
    int bad = 0;
    #pragma unroll
    for (int l = 0; l < 2; l++) {
        long long v = e[lane + 32 * l];
        bad |= (v < 0 || v >= NN);
    }
    unsigned m = __ballot_sync(0xffffffffu, bad);
    if (lane == 0) g_is64 = (m == 0u);
}

// ---------------- graph preprocessing ----------------
__global__ void k_count(const void* e) {
    int i = blockIdx.x * blockDim.x + threadIdx.x;
    if (i < EE) {
        int d = edge_at(e, (long long)EE + i);
        atomicAdd(&g_cnt[d], 1);
    }
}

__global__ void k_bsum() {
    __shared__ int sh[256];
    int i = blockIdx.x * 256 + threadIdx.x;
    sh[threadIdx.x] = (i < NN) ? g_cnt[i] : 0;
    __syncthreads();
    for (int s = 128; s > 0; s >>= 1) {
        if (threadIdx.x < s) sh[threadIdx.x] += sh[threadIdx.x + s];
        __syncthreads();
    }
    if (threadIdx.x == 0) g_bsum[blockIdx.x] = sh[0];
}

__global__ void k_scan_bsum() {
    __shared__ int sh[256];
    int t = threadIdx.x;
    int v = (t < SCAN_B) ? g_bsum[t] : 0;
    sh[t] = v;
    __syncthreads();
    for (int off = 1; off < 256; off <<= 1) {
        int tv = (t >= off) ? sh[t - off] : 0;
        __syncthreads();
        sh[t] += tv;
        __syncthreads();
    }
    if (t < SCAN_B) g_bsum[t] = sh[t] - v;
    if (t == 255) g_rowptr[NN] = sh[255];
}

__global__ void k_scan_final() {
    __shared__ int sh[256];
    int t = threadIdx.x;
    int i = blockIdx.x * 256 + t;
    int v = (i < NN) ? g_cnt[i] : 0;
    sh[t] = v;
    __syncthreads();
    for (int off = 1; off < 256; off <<= 1) {
        int tv = (t >= off) ? sh[t - off] : 0;
        __syncthreads();
        sh[t] += tv;
        __syncthreads();
    }
    int excl = sh[t] - v + g_bsum[blockIdx.x];
    if (i < NN) {
        g_rowptr[i] = excl;
        g_pos[i]    = excl;
        g_dinv[i]   = rsqrtf((float)v + 1.0f);   // +1 self loop
    }
}

__global__ void k_fill(const void* e) {
    int i = blockIdx.x * blockDim.x + threadIdx.x;
    if (i < EE) {
        int s = edge_at(e, i);
        int d = edge_at(e, (long long)EE + i);
        int p = atomicAdd(&g_pos[d], 1);
        int2 ew;
        ew.x = s;
        ew.y = __float_as_int(g_dinv[s] * g_dinv[d]);
        g_edge[p] = ew;
    }
}

// ------- hop 1: gather fp16 Zh rows; power-1 -> H fp32, A*z2 -> Th fp16 --------
__global__ __launch_bounds__(256) void spmm128h(
    const __half* __restrict__ Zh, float* __restrict__ H, __half* __restrict__ Th)
{
    int warp = (blockIdx.x * blockDim.x + threadIdx.x) >> 5;
    int lane = threadIdx.x & 31;
    if (warp >= NN) return;
    float dv = g_dinv[warp];
    float ws = dv * dv;
    uint2 zp = ((const uint2*)(Zh + (size_t)warp * 128))[lane];     // 4 halves
    float2 z0 = __half22float2(*(const __half2*)&zp.x);
    float2 z1 = __half22float2(*(const __half2*)&zp.y);
    float a0 = ws * z0.x, a1 = ws * z0.y, a2 = ws * z1.x, a3 = ws * z1.y;
    int e0 = g_rowptr[warp], e1 = g_rowptr[warp + 1];
    #pragma unroll 4
    for (int e = e0; e < e1; e++) {
        int2 ew  = __ldg(&g_edge[e]);
        int c    = ew.x;
        float wt = __int_as_float(ew.y);
        uint2 vp = ((const uint2*)(Zh + (size_t)c * 128))[lane];
        float2 v0 = __half22float2(*(const __half2*)&vp.x);
        float2 v1 = __half22float2(*(const __half2*)&vp.y);
        a0 = fmaf(wt, v0.x, a0);
        a1 = fmaf(wt, v0.y, a1);
        a2 = fmaf(wt, v1.x, a2);
        a3 = fmaf(wt, v1.y, a3);
    }
    if (lane < 16) {
        float4 o; o.x = a0; o.y = a1; o.z = a2; o.w = a3;
        *(float4*)(H + (size_t)warp * C1 + HIDD + lane * 4) = o;
    } else {
        uint2 op;
        *(__half2*)&op.x = __floats2half2_rn(a0, a1);
        *(__half2*)&op.y = __floats2half2_rn(a2, a3);
        *(uint2*)(Th + (size_t)warp * HIDD + (lane - 16) * 4) = op;
    }
}

// ------- hop 2: gather fp16 Th rows; power-2 -> H fp32 --------------------------
__global__ __launch_bounds__(256) void spmm64h(
    const __half* __restrict__ Th, float* __restrict__ H)
{
    int warp = (blockIdx.x * blockDim.x + threadIdx.x) >> 5;
    int lane = threadIdx.x & 31;
    if (warp >= NN) return;
    float dv = g_dinv[warp];
    float ws = dv * dv;
    uint32_t zp = ((const uint32_t*)(Th + (size_t)warp * HIDD))[lane];
    float2 z = __half22float2(*(const __half2*)&zp);
    float ax = ws * z.x, ay = ws * z.y;
    int e0 = g_rowptr[warp], e1 = g_rowptr[warp + 1];
    #pragma unroll 4
    for (int e = e0; e < e1; e++) {
        int2 ew  = __ldg(&g_edge[e]);
        int c    = ew.x;
        float wt = __int_as_float(ew.y);
        uint32_t vp = ((const uint32_t*)(Th + (size_t)c * HIDD))[lane];
        float2 v = __half22float2(*(const __half2*)&vp);
        ax = fmaf(wt, v.x, ax);
        ay = fmaf(wt, v.y, ay);
    }
    float2 o; o.x = ax; o.y = ay;
    *(float2*)(H + (size_t)warp * C1 + 2 * HIDD + lane * 2) = o;
}

// ---------------- BatchNorm stats (sum+sumsq into g_stats) ----------------
__global__ void bn_stats(const float* __restrict__ H) {
    int c = threadIdx.x;
    float s = 0.f, q = 0.f;
    for (int r = blockIdx.x; r < NN; r += gridDim.x) {
        float v = H[(size_t)r * C1 + c];
        s += v;
        q = fmaf(v, v, q);
    }
    atomicAdd(&g_stats[c], s);
    atomicAdd(&g_stats[C1 + c], q);
}

// ------------- bf16 split-2 tensor-core GEMM (m16n8k16, 3-term compensation) ----
// Register-prefetch pipelined: next tile's gmem loads issue before the MMA block.
// out = act(A)[M,K] @ W[p][K,64] (+bias); act = BN+ReLU from g_stats when gvec.
// p==0 -> fp32 store into dup (ld C1); p>=1 -> fp16 store into duph (ld 128);
// C (ld NC) stored only if non-null (final FC).
#define BM 128
#define BN 64
#define BK 32
#define KP 16
#define AST 20
#define BST 72

__device__ __forceinline__ uint32_t pack_bf16(float x, float y) {
    __nv_bfloat162 t;
    t.x = __float2bfloat16_rn(x);
    t.y = __float2bfloat16_rn(y);
    return *reinterpret_cast<uint32_t*>(&t);
}
__device__ __forceinline__ float bf_hi_f(float x) {
    return __bfloat162float(__float2bfloat16_rn(x));
}

__device__ __forceinline__ void mma_bf16(float* d, const uint32_t* a, const uint32_t* b) {
    asm volatile(
        "mma.sync.aligned.m16n8k16.row.col.f32.bf16.bf16.f32 "
        "{%0,%1,%2,%3},{%4,%5,%6,%7},{%8,%9},{%0,%1,%2,%3};\n"
        : "+f"(d[0]), "+f"(d[1]), "+f"(d[2]), "+f"(d[3])
        : "r"(a[0]), "r"(a[1]), "r"(a[2]), "r"(a[3]), "r"(b[0]), "r"(b[1]));
}

__global__ __launch_bounds__(256, 2) void tgemm(
    const float* __restrict__ A, const float* __restrict__ Bmat,
    float* __restrict__ C, int M, int K, int NC,
    const float* __restrict__ bias,
    const float* __restrict__ gvec, const float* __restrict__ bevec,
    float* __restrict__ dup, __half* __restrict__ duph)
{
    __shared__ uint32_t AsH[BM * AST];
    __shared__ uint32_t AsL[BM * AST];
    __shared__ uint32_t BsH[KP * BST];
    __shared__ uint32_t BsL[KP * BST];
    __shared__ float sSc[C1];
    __shared__ float sSh[C1];
    int p = blockIdx.y;
    const float* Bp = Bmat + (size_t)p * K * BN;
    int rowBase = blockIdx.x * BM;
    int tid  = threadIdx.x;
    int lane = tid & 31;
    int w    = tid >> 5;
    int wm   = w & 3;
    int wn   = w >> 2;
    int lr   = lane >> 2;
    int lc   = lane & 3;

    bool hasbn = (gvec != nullptr);
    if (hasbn) {
        if (tid < C1) {
            float mu  = g_stats[tid] * (1.0f / NN);
            float var = g_stats[C1 + tid] * (1.0f / NN) - mu * mu;
            float inv = rsqrtf(var + EPSB);
            float sc  = inv * gvec[tid];
            sSc[tid] = sc;
            sSh[tid] = bevec[tid] - mu * sc;
        }
        __syncthreads();
    }

    // per-thread load coordinates
    const int ar  = tid >> 3;            // row within tile for l=0 (stride 32 per l)
    const int ac4 = tid & 7;             // float4 index over k
    const int bkp = tid >> 4;            // 0..15 k-pair row
    const int bn4 = tid & 15;            // n4 group

    float acc[2][4][4];
    #pragma unroll
    for (int mt = 0; mt < 2; mt++)
        #pragma unroll
        for (int nt = 0; nt < 4; nt++)
            #pragma unroll
            for (int i = 0; i < 4; i++) acc[mt][nt][i] = 0.f;

    float4 avA[4];
    float4 avB0, avB1;
    // prefetch tile 0
    #pragma unroll
    for (int l = 0; l < 4; l++) {
        int grow = rowBase + ar + l * 32;
        avA[l] = (grow < M) ? *(const float4*)(A + (size_t)grow * K + ac4 * 4)
                            : make_float4(0.f, 0.f, 0.f, 0.f);
    }
    {
        const float* r0p = Bp + (size_t)(2 * bkp) * BN + bn4 * 4;
        avB0 = *(const float4*)r0p;
        avB1 = *(const float4*)(r0p + BN);
    }

    for (int k0 = 0; k0 < K; k0 += BK) {
        // ---- pack current registers into smem (BN+ReLU applied here) ----
        #pragma unroll
        for (int l = 0; l < 4; l++) {
            float4 v = avA[l];
            if (hasbn) {
                int kc = k0 + ac4 * 4;
                v.x = fmaxf(0.f, fmaf(v.x, sSc[kc + 0], sSh[kc + 0]));
                v.y = fmaxf(0.f, fmaf(v.y, sSc[kc + 1], sSh[kc + 1]));
                v.z = fmaxf(0.f, fmaf(v.z, sSc[kc + 2], sSh[kc + 2]));
                v.w = fmaxf(0.f, fmaf(v.w, sSc[kc + 3], sSh[kc + 3]));
            }
            int row = ar + l * 32;
            int kp  = ac4 * 2;
            AsH[row * AST + kp]     = pack_bf16(v.x, v.y);
            AsH[row * AST + kp + 1] = pack_bf16(v.z, v.w);
            AsL[row * AST + kp]     = pack_bf16(v.x - bf_hi_f(v.x), v.y - bf_hi_f(v.y));
            AsL[row * AST + kp + 1] = pack_bf16(v.z - bf_hi_f(v.z), v.w - bf_hi_f(v.w));
        }
        {
            float4 u0 = avB0, u1 = avB1;
            uint32_t* dh = &BsH[bkp * BST + bn4 * 4];
            uint32_t* dl = &BsL[bkp * BST + bn4 * 4];
            dh[0] = pack_bf16(u0.x, u1.x);
            dh[1] = pack_bf16(u0.y, u1.y);
            dh[2] = pack_bf16(u0.z, u1.z);
            dh[3] = pack_bf16(u0.w, u1.w);
            dl[0] = pack_bf16(u0.x - bf_hi_f(u0.x), u1.x - bf_hi_f(u1.x));
            dl[1] = pack_bf16(u0.y - bf_hi_f(u0.y), u1.y - bf_hi_f(u1.y));
            dl[2] = pack_bf16(u0.z - bf_hi_f(u0.z), u1.z - bf_hi_f(u1.z));
            dl[3] = pack_bf16(u0.w - bf_hi_f(u0.w), u1.w - bf_hi_f(u1.w));
        }
        __syncthreads();

        // ---- prefetch next tile into registers (hides behind MMA block) ----
        int kn = k0 + BK;
        if (kn < K) {
            #pragma unroll
            for (int l = 0; l < 4; l++) {
                int grow = rowBase + ar + l * 32;
                avA[l] = (grow < M) ? *(const float4*)(A + (size_t)grow * K + kn + ac4 * 4)
                                    : make_float4(0.f, 0.f, 0.f, 0.f);
            }
            const float* r0p = Bp + (size_t)(kn + 2 * bkp) * BN + bn4 * 4;
            avB0 = *(const float4*)r0p;
            avB1 = *(const float4*)(r0p + BN);
        }

        // ---- MMAs on current smem tile ----
        #pragma unroll
        for (int c = 0; c < 2; c++) {
            int kpb = c * 8;
            uint32_t ahi[2][4], alo[2][4];
            #pragma unroll
            for (int mt = 0; mt < 2; mt++) {
                int r0 = wm * 32 + mt * 16 + lr;
                ahi[mt][0] = AsH[r0 * AST + kpb + lc];
                ahi[mt][1] = AsH[(r0 + 8) * AST + kpb + lc];
                ahi[mt][2] = AsH[r0 * AST + kpb + lc + 4];
                ahi[mt][3] = AsH[(r0 + 8) * AST + kpb + lc + 4];
                alo[mt][0] = AsL[r0 * AST + kpb + lc];
                alo[mt][1] = AsL[(r0 + 8) * AST + kpb + lc];
                alo[mt][2] = AsL[r0 * AST + kpb + lc + 4];
                alo[mt][3] = AsL[(r0 + 8) * AST + kpb + lc + 4];
            }
            uint32_t bhi[4][2], blo[4][2];
            #pragma unroll
            for (int nt = 0; nt < 4; nt++) {
                int n0 = wn * 32 + nt * 8 + lr;
                bhi[nt][0] = BsH[(kpb + lc) * BST + n0];
                bhi[nt][1] = BsH[(kpb + lc + 4) * BST + n0];
                blo[nt][0] = BsL[(kpb + lc) * BST + n0];
                blo[nt][1] = BsL[(kpb + lc + 4) * BST + n0];
            }
            #pragma unroll
            for (int mt = 0; mt < 2; mt++)
                #pragma unroll
                for (int nt = 0; nt < 4; nt++) {
                    mma_bf16(acc[mt][nt], ahi[mt], bhi[nt]);
                    mma_bf16(acc[mt][nt], ahi[mt], blo[nt]);
                    mma_bf16(acc[mt][nt], alo[mt], bhi[nt]);
                }
        }
        __syncthreads();
    }

    #pragma unroll
    for (int mt = 0; mt < 2; mt++) {
        #pragma unroll
        for (int nt = 0; nt < 4; nt++) {
            int ncol = wn * 32 + nt * 8 + lc * 2;
            int gcol = p * BN + ncol;
            float bx = 0.f, by = 0.f;
            if (bias) { bx = bias[ncol]; by = bias[ncol + 1]; }
            #pragma unroll
            for (int hh = 0; hh < 2; hh++) {
                int r = rowBase + wm * 32 + mt * 16 + lr + hh * 8;
                if (r < M) {
                    float ox = acc[mt][nt][2 * hh]     + bx;
                    float oy = acc[mt][nt][2 * hh + 1] + by;
                    if (C) {
                        float2 o; o.x = ox; o.y = oy;
                        *(float2*)(C + (size_t)r * NC + gcol) = o;
                    }
                    if (p == 0) {
                        if (dup) {
                            float2 o; o.x = ox; o.y = oy;
                            *(float2*)(dup + (size_t)r * C1 + gcol) = o;
                        }
                    } else if (duph) {
                        __half2 h = __floats2half2_rn(ox, oy);
                        *(__half2*)(duph + (size_t)r * 128 + (gcol - BN)) = h;
                    }
                }
            }
        }
    }
}

// ---------------- host launch ----------------
extern "C" void kernel_launch(void* const* d_in, const int* in_sizes, int n_in,
                              void* d_out, int out_size) {
    const float* x   = (const float*)d_in[0];
    const void*  ei  = d_in[1];
    const float* W1  = (const float*)d_in[2];
    // d_in[3] = B1 (absorbed by BatchNorm)
    const float* g1  = (const float*)d_in[4];
    const float* be1 = (const float*)d_in[5];
    const float* W2  = (const float*)d_in[6];
    // d_in[7] = B2 (absorbed by BatchNorm)
    const float* g2  = (const float*)d_in[8];
    const float* be2 = (const float*)d_in[9];
    const float* Wfc = (const float*)d_in[10];
    const float* bfc = (const float*)d_in[11];
    float* out = (float*)d_out;

    float *Hpre, *H2, *St;
    __half *Zh, *Th;
    int *Cnt;
    cudaGetSymbolAddress((void**)&Zh,   g_Zh);
    cudaGetSymbolAddress((void**)&Th,   g_Th);
    cudaGetSymbolAddress((void**)&Hpre, g_Hpre);
    cudaGetSymbolAddress((void**)&H2,   g_H2);
    cudaGetSymbolAddress((void**)&St,   g_stats);
    cudaGetSymbolAddress((void**)&Cnt,  g_cnt);

    static cudaStream_t sB = nullptr;
    static cudaEvent_t evFork = nullptr, evJoin = nullptr;
    if (!sB) {
        cudaStreamCreateWithFlags(&sB, cudaStreamNonBlocking);
        cudaEventCreateWithFlags(&evFork, cudaEventDisableTiming);
        cudaEventCreateWithFlags(&evJoin, cudaEventDisableTiming);
    }

    const int TB = 256;
    const int nBlkE  = (EE + TB - 1) / TB;
    const int nBlkSp = (NN + 7) / 8;
    const dim3 gemmG((NN + BM - 1) / BM, 3);
    const dim3 gemmO((NN + BM - 1) / BM, 1);

    // ---- fork: CSR preprocessing on side stream, layer-1 GEMM on main --------
    cudaEventRecord(evFork, 0);
    cudaStreamWaitEvent(sB, evFork, 0);

    k_detect<<<1, 32, 0, sB>>>((const long long*)ei);
    cudaMemsetAsync(Cnt, 0, NN * sizeof(int), sB);
    k_count<<<nBlkE, TB, 0, sB>>>(ei);
    k_bsum<<<SCAN_B, 256, 0, sB>>>();
    k_scan_bsum<<<1, 256, 0, sB>>>();
    k_scan_final<<<SCAN_B, 256, 0, sB>>>();
    k_fill<<<nBlkE, TB, 0, sB>>>(ei);
    cudaEventRecord(evJoin, sB);

    // main stream: layer-1 GEMM (independent of graph preprocessing)
    tgemm<<<gemmG, TB>>>(x, W1, nullptr, NN, FIN, C1, nullptr, nullptr, nullptr, Hpre, Zh);
    cudaMemsetAsync(St, 0, 2 * C1 * sizeof(float));   // stats for layer 1

    cudaStreamWaitEvent(0, evJoin, 0);                // join: SpMM needs CSR + Zh

    // ---- layer 1 propagation + stats ----
    spmm128h<<<nBlkSp, TB>>>(Zh, Hpre, Th);
    spmm64h<<<nBlkSp, TB>>>(Th, Hpre);
    bn_stats<<<512, C1>>>(Hpre);

    // ---- layer 2 (BN1+ReLU folded into GEMM prologue from g_stats) ----
    tgemm<<<gemmG, TB>>>(Hpre, W2, nullptr, NN, C1, C1, nullptr, g1, be1, H2, Zh);
    cudaMemsetAsync(St, 0, 2 * C1 * sizeof(float));   // stats for layer 2 (after tgemm read)
    spmm128h<<<nBlkSp, TB>>>(Zh, H2, Th);
    spmm64h<<<nBlkSp, TB>>>(Th, H2);
    bn_stats<<<512, C1>>>(H2);

    // ---- final fc (BN2+ReLU folded into GEMM prologue) ----
    tgemm<<<gemmO, TB>>>(H2, Wfc, out, NN, C1, HIDD, bfc, g2, be2, nullptr, nullptr);

    (void)in_sizes; (void)n_in; (void)out_size;
}

// round 11
// speedup vs baseline: 1.7390x; 1.0294x over previous
#include <cuda_runtime.h>
#include <cuda_bf16.h>
#include <cuda_fp16.h>
#include <cstdint>

#define NN   50000
#define EE   800000
#define FIN  128
#define HIDD 64
#define C1   192          // P*HID
#define EPSB 1e-5f
#define SCAN_B 196        // ceil(NN/256)

// ---------------- static device scratch (no allocations allowed) ----------------
__device__ int g_is64;
__device__ __align__(256) __half g_Zh [(size_t)NN * 128];   // fp16 cols 64..191 of layer GEMM out
__device__ __align__(256) __half g_Th [(size_t)NN * HIDD];  // fp16 hop-1 intermediate
__device__ __align__(256) float g_Hpre[(size_t)NN * C1];
__device__ __align__(256) float g_H2  [(size_t)NN * C1];
__device__ int   g_cnt[NN];
__device__ int   g_rowptr[NN + 1];
__device__ int   g_pos[NN];
__device__ int   g_bsum[SCAN_B];
__device__ __align__(256) int2  g_edge[EE];        // {col, w as float bits}
__device__ float g_dinv[NN];
// two stat buffers (layer1 / layer2); each: [0..C1) sums, [C1..2C1) sumsq
__device__ __align__(256) float g_stats[2][2 * C1];

// ---------------- edge index accessor (dtype-agnostic) ----------------
__device__ __forceinline__ int edge_at(const void* p, long long i) {
    if (g_is64) return (int)((const long long*)p)[i];
    return ((const int*)p)[i];
}

__global__ void k_detect(const long long* e) {
    int lane = threadIdx.x;
    int bad = 0;
    #pragma unroll
    for (int l = 0; l < 2; l++) {
        long long v = e[lane + 32 * l];
        bad |= (v < 0 || v >= NN);
    }
    unsigned m = __ballot_sync(0xffffffffu, bad);
    if (lane == 0) g_is64 = (m == 0u);
}

// ---------------- graph preprocessing ----------------
__global__ void k_count(const void* e) {
    int i = blockIdx.x * blockDim.x + threadIdx.x;
    if (i < EE) {
        int d = edge_at(e, (long long)EE + i);
        atomicAdd(&g_cnt[d], 1);
    }
}

__global__ void k_bsum() {
    __shared__ int sh[256];
    int i = blockIdx.x * 256 + threadIdx.x;
    sh[threadIdx.x] = (i < NN) ? g_cnt[i] : 0;
    __syncthreads();
    for (int s = 128; s > 0; s >>= 1) {
        if (threadIdx.x < s) sh[threadIdx.x] += sh[threadIdx.x + s];
        __syncthreads();
    }
    if (threadIdx.x == 0) g_bsum[blockIdx.x] = sh[0];
}

__global__ void k_scan_bsum() {
    __shared__ int sh[256];
    int t = threadIdx.x;
    int v = (t < SCAN_B) ? g_bsum[t] : 0;
    sh[t] = v;
    __syncthreads();
    for (int off = 1; off < 256; off <<= 1) {
        int tv = (t >= off) ? sh[t - off] : 0;
        __syncthreads();
        sh[t] += tv;
        __syncthreads();
    }
    if (t < SCAN_B) g_bsum[t] = sh[t] - v;
    if (t == 255) g_rowptr[NN] = sh[255];
}

__global__ void k_scan_final() {
    __shared__ int sh[256];
    int t = threadIdx.x;
    int i = blockIdx.x * 256 + t;
    int v = (i < NN) ? g_cnt[i] : 0;
    sh[t] = v;
    __syncthreads();
    for (int off = 1; off < 256; off <<= 1) {
        int tv = (t >= off) ? sh[t - off] : 0;
        __syncthreads();
        sh[t] += tv;
        __syncthreads();
    }
    int excl = sh[t] - v + g_bsum[blockIdx.x];
    if (i < NN) {
        g_rowptr[i] = excl;
        g_pos[i]    = excl;
        g_dinv[i]   = rsqrtf((float)v + 1.0f);   // +1 self loop
    }
}

__global__ void k_fill(const void* e) {
    int i = blockIdx.x * blockDim.x + threadIdx.x;
    if (i < EE) {
        int s = edge_at(e, i);
        int d = edge_at(e, (long long)EE + i);
        int p = atomicAdd(&g_pos[d], 1);
        int2 ew;
        ew.x = s;
        ew.y = __float_as_int(g_dinv[s] * g_dinv[d]);
        g_edge[p] = ew;
    }
}

// ------- hop 1: gather fp16 Zh rows; power-1 -> H fp32 (+stats), A*z2 -> Th ----
// grid is exact: 6250 blocks x 8 warps = NN rows, no inactive warps.
__global__ __launch_bounds__(256) void spmm128h(
    const __half* __restrict__ Zh, float* __restrict__ H, __half* __restrict__ Th,
    float* __restrict__ stats)
{
    __shared__ float sS[64], sQ[64];
    if (threadIdx.x < 64) { sS[threadIdx.x] = 0.f; sQ[threadIdx.x] = 0.f; }
    __syncthreads();

    int warp = (blockIdx.x * blockDim.x + threadIdx.x) >> 5;
    int lane = threadIdx.x & 31;
    float dv = g_dinv[warp];
    float ws = dv * dv;
    uint2 zp = ((const uint2*)(Zh + (size_t)warp * 128))[lane];     // 4 halves
    float2 z0 = __half22float2(*(const __half2*)&zp.x);
    float2 z1 = __half22float2(*(const __half2*)&zp.y);
    float a0 = ws * z0.x, a1 = ws * z0.y, a2 = ws * z1.x, a3 = ws * z1.y;
    int e0 = g_rowptr[warp], e1 = g_rowptr[warp + 1];
    #pragma unroll 4
    for (int e = e0; e < e1; e++) {
        int2 ew  = __ldg(&g_edge[e]);
        int c    = ew.x;
        float wt = __int_as_float(ew.y);
        uint2 vp = ((const uint2*)(Zh + (size_t)c * 128))[lane];
        float2 v0 = __half22float2(*(const __half2*)&vp.x);
        float2 v1 = __half22float2(*(const __half2*)&vp.y);
        a0 = fmaf(wt, v0.x, a0);
        a1 = fmaf(wt, v0.y, a1);
        a2 = fmaf(wt, v1.x, a2);
        a3 = fmaf(wt, v1.y, a3);
    }
    if (lane < 16) {
        float4 o; o.x = a0; o.y = a1; o.z = a2; o.w = a3;
        *(float4*)(H + (size_t)warp * C1 + HIDD + lane * 4) = o;
        int b = lane * 4;
        atomicAdd(&sS[b + 0], a0); atomicAdd(&sQ[b + 0], a0 * a0);
        atomicAdd(&sS[b + 1], a1); atomicAdd(&sQ[b + 1], a1 * a1);
        atomicAdd(&sS[b + 2], a2); atomicAdd(&sQ[b + 2], a2 * a2);
        atomicAdd(&sS[b + 3], a3); atomicAdd(&sQ[b + 3], a3 * a3);
    } else {
        uint2 op;
        *(__half2*)&op.x = __floats2half2_rn(a0, a1);
        *(__half2*)&op.y = __floats2half2_rn(a2, a3);
        *(uint2*)(Th + (size_t)warp * HIDD + (lane - 16) * 4) = op;
    }
    __syncthreads();
    if (threadIdx.x < 64) {
        atomicAdd(&stats[HIDD + threadIdx.x], sS[threadIdx.x]);
        atomicAdd(&stats[C1 + HIDD + threadIdx.x], sQ[threadIdx.x]);
    }
}

// ------- hop 2: gather fp16 Th rows; power-2 -> H fp32 (+stats) -----------------
__global__ __launch_bounds__(256) void spmm64h(
    const __half* __restrict__ Th, float* __restrict__ H, float* __restrict__ stats)
{
    __shared__ float sS[64], sQ[64];
    if (threadIdx.x < 64) { sS[threadIdx.x] = 0.f; sQ[threadIdx.x] = 0.f; }
    __syncthreads();

    int warp = (blockIdx.x * blockDim.x + threadIdx.x) >> 5;
    int lane = threadIdx.x & 31;
    float dv = g_dinv[warp];
    float ws = dv * dv;
    uint32_t zp = ((const uint32_t*)(Th + (size_t)warp * HIDD))[lane];
    float2 z = __half22float2(*(const __half2*)&zp);
    float ax = ws * z.x, ay = ws * z.y;
    int e0 = g_rowptr[warp], e1 = g_rowptr[warp + 1];
    #pragma unroll 4
    for (int e = e0; e < e1; e++) {
        int2 ew  = __ldg(&g_edge[e]);
        int c    = ew.x;
        float wt = __int_as_float(ew.y);
        uint32_t vp = ((const uint32_t*)(Th + (size_t)c * HIDD))[lane];
        float2 v = __half22float2(*(const __half2*)&vp);
        ax = fmaf(wt, v.x, ax);
        ay = fmaf(wt, v.y, ay);
    }
    float2 o; o.x = ax; o.y = ay;
    *(float2*)(H + (size_t)warp * C1 + 2 * HIDD + lane * 2) = o;
    int b = lane * 2;
    atomicAdd(&sS[b + 0], ax); atomicAdd(&sQ[b + 0], ax * ax);
    atomicAdd(&sS[b + 1], ay); atomicAdd(&sQ[b + 1], ay * ay);
    __syncthreads();
    if (threadIdx.x < 64) {
        atomicAdd(&stats[2 * HIDD + threadIdx.x], sS[threadIdx.x]);
        atomicAdd(&stats[C1 + 2 * HIDD + threadIdx.x], sQ[threadIdx.x]);
    }
}

// ------------- bf16 split-2 tensor-core GEMM (m16n8k16, 3-term compensation) ----
// Register-prefetch pipelined. BN+ReLU on A computed from statsIn when gvec.
// p==0: fp32 store into dup (ld C1) and power-0 stats into statsOut.
// p>=1: fp16 store into duph (ld 128). C (ld NC) stored only if non-null.
#define BM 128
#define BN 64
#define BK 32
#define KP 16
#define AST 20
#define BST 72

__device__ __forceinline__ uint32_t pack_bf16(float x, float y) {
    __nv_bfloat162 t;
    t.x = __float2bfloat16_rn(x);
    t.y = __float2bfloat16_rn(y);
    return *reinterpret_cast<uint32_t*>(&t);
}
__device__ __forceinline__ float bf_hi_f(float x) {
    return __bfloat162float(__float2bfloat16_rn(x));
}

__device__ __forceinline__ void mma_bf16(float* d, const uint32_t* a, const uint32_t* b) {
    asm volatile(
        "mma.sync.aligned.m16n8k16.row.col.f32.bf16.bf16.f32 "
        "{%0,%1,%2,%3},{%4,%5,%6,%7},{%8,%9},{%0,%1,%2,%3};\n"
        : "+f"(d[0]), "+f"(d[1]), "+f"(d[2]), "+f"(d[3])
        : "r"(a[0]), "r"(a[1]), "r"(a[2]), "r"(a[3]), "r"(b[0]), "r"(b[1]));
}

__global__ __launch_bounds__(256, 2) void tgemm(
    const float* __restrict__ A, const float* __restrict__ Bmat,
    float* __restrict__ C, int M, int K, int NC,
    const float* __restrict__ bias,
    const float* __restrict__ gvec, const float* __restrict__ bevec,
    const float* __restrict__ statsIn,
    float* __restrict__ dup, __half* __restrict__ duph,
    float* __restrict__ statsOut)
{
    __shared__ uint32_t AsH[BM * AST];
    __shared__ uint32_t AsL[BM * AST];
    __shared__ uint32_t BsH[KP * BST];
    __shared__ uint32_t BsL[KP * BST];
    __shared__ float sSc[C1];
    __shared__ float sSh[C1];
    __shared__ float sSum[64];
    __shared__ float sSq[64];
    int p = blockIdx.y;
    const float* Bp = Bmat + (size_t)p * K * BN;
    int rowBase = blockIdx.x * BM;
    int tid  = threadIdx.x;
    int lane = tid & 31;
    int w    = tid >> 5;
    int wm   = w & 3;
    int wn   = w >> 2;
    int lr   = lane >> 2;
    int lc   = lane & 3;

    bool hasbn = (gvec != nullptr);
    bool dostats = (statsOut != nullptr) && (p == 0);
    if (tid < 64) { sSum[tid] = 0.f; sSq[tid] = 0.f; }
    if (hasbn && tid < C1) {
        float mu  = statsIn[tid] * (1.0f / NN);
        float var = statsIn[C1 + tid] * (1.0f / NN) - mu * mu;
        float inv = rsqrtf(var + EPSB);
        float sc  = inv * gvec[tid];
        sSc[tid] = sc;
        sSh[tid] = bevec[tid] - mu * sc;
    }
    __syncthreads();

    const int ar  = tid >> 3;
    const int ac4 = tid & 7;
    const int bkp = tid >> 4;
    const int bn4 = tid & 15;

    float acc[2][4][4];
    #pragma unroll
    for (int mt = 0; mt < 2; mt++)
        #pragma unroll
        for (int nt = 0; nt < 4; nt++)
            #pragma unroll
            for (int i = 0; i < 4; i++) acc[mt][nt][i] = 0.f;

    float4 avA[4];
    float4 avB0, avB1;
    #pragma unroll
    for (int l = 0; l < 4; l++) {
        int grow = rowBase + ar + l * 32;
        avA[l] = (grow < M) ? *(const float4*)(A + (size_t)grow * K + ac4 * 4)
                            : make_float4(0.f, 0.f, 0.f, 0.f);
    }
    {
        const float* r0p = Bp + (size_t)(2 * bkp) * BN + bn4 * 4;
        avB0 = *(const float4*)r0p;
        avB1 = *(const float4*)(r0p + BN);
    }

    for (int k0 = 0; k0 < K; k0 += BK) {
        #pragma unroll
        for (int l = 0; l < 4; l++) {
            float4 v = avA[l];
            if (hasbn) {
                int kc = k0 + ac4 * 4;
                v.x = fmaxf(0.f, fmaf(v.x, sSc[kc + 0], sSh[kc + 0]));
                v.y = fmaxf(0.f, fmaf(v.y, sSc[kc + 1], sSh[kc + 1]));
                v.z = fmaxf(0.f, fmaf(v.z, sSc[kc + 2], sSh[kc + 2]));
                v.w = fmaxf(0.f, fmaf(v.w, sSc[kc + 3], sSh[kc + 3]));
            }
            int row = ar + l * 32;
            int kp  = ac4 * 2;
            AsH[row * AST + kp]     = pack_bf16(v.x, v.y);
            AsH[row * AST + kp + 1] = pack_bf16(v.z, v.w);
            AsL[row * AST + kp]     = pack_bf16(v.x - bf_hi_f(v.x), v.y - bf_hi_f(v.y));
            AsL[row * AST + kp + 1] = pack_bf16(v.z - bf_hi_f(v.z), v.w - bf_hi_f(v.w));
        }
        {
            float4 u0 = avB0, u1 = avB1;
            uint32_t* dh = &BsH[bkp * BST + bn4 * 4];
            uint32_t* dl = &BsL[bkp * BST + bn4 * 4];
            dh[0] = pack_bf16(u0.x, u1.x);
            dh[1] = pack_bf16(u0.y, u1.y);
            dh[2] = pack_bf16(u0.z, u1.z);
            dh[3] = pack_bf16(u0.w, u1.w);
            dl[0] = pack_bf16(u0.x - bf_hi_f(u0.x), u1.x - bf_hi_f(u1.x));
            dl[1] = pack_bf16(u0.y - bf_hi_f(u0.y), u1.y - bf_hi_f(u1.y));
            dl[2] = pack_bf16(u0.z - bf_hi_f(u0.z), u1.z - bf_hi_f(u1.z));
            dl[3] = pack_bf16(u0.w - bf_hi_f(u0.w), u1.w - bf_hi_f(u1.w));
        }
        __syncthreads();

        int kn = k0 + BK;
        if (kn < K) {
            #pragma unroll
            for (int l = 0; l < 4; l++) {
                int grow = rowBase + ar + l * 32;
                avA[l] = (grow < M) ? *(const float4*)(A + (size_t)grow * K + kn + ac4 * 4)
                                    : make_float4(0.f, 0.f, 0.f, 0.f);
            }
            const float* r0p = Bp + (size_t)(kn + 2 * bkp) * BN + bn4 * 4;
            avB0 = *(const float4*)r0p;
            avB1 = *(const float4*)(r0p + BN);
        }

        #pragma unroll
        for (int c = 0; c < 2; c++) {
            int kpb = c * 8;
            uint32_t ahi[2][4], alo[2][4];
            #pragma unroll
            for (int mt = 0; mt < 2; mt++) {
                int r0 = wm * 32 + mt * 16 + lr;
                ahi[mt][0] = AsH[r0 * AST + kpb + lc];
                ahi[mt][1] = AsH[(r0 + 8) * AST + kpb + lc];
                ahi[mt][2] = AsH[r0 * AST + kpb + lc + 4];
                ahi[mt][3] = AsH[(r0 + 8) * AST + kpb + lc + 4];
                alo[mt][0] = AsL[r0 * AST + kpb + lc];
                alo[mt][1] = AsL[(r0 + 8) * AST + kpb + lc];
                alo[mt][2] = AsL[r0 * AST + kpb + lc + 4];
                alo[mt][3] = AsL[(r0 + 8) * AST + kpb + lc + 4];
            }
            uint32_t bhi[4][2], blo[4][2];
            #pragma unroll
            for (int nt = 0; nt < 4; nt++) {
                int n0 = wn * 32 + nt * 8 + lr;
                bhi[nt][0] = BsH[(kpb + lc) * BST + n0];
                bhi[nt][1] = BsH[(kpb + lc + 4) * BST + n0];
                blo[nt][0] = BsL[(kpb + lc) * BST + n0];
                blo[nt][1] = BsL[(kpb + lc + 4) * BST + n0];
            }
            #pragma unroll
            for (int mt = 0; mt < 2; mt++)
                #pragma unroll
                for (int nt = 0; nt < 4; nt++) {
                    mma_bf16(acc[mt][nt], ahi[mt], bhi[nt]);
                    mma_bf16(acc[mt][nt], ahi[mt], blo[nt]);
                    mma_bf16(acc[mt][nt], alo[mt], bhi[nt]);
                }
        }
        __syncthreads();
    }

    #pragma unroll
    for (int nt = 0; nt < 4; nt++) {
        int ncol = wn * 32 + nt * 8 + lc * 2;
        int gcol = p * BN + ncol;
        float bx = 0.f, by = 0.f;
        if (bias) { bx = bias[ncol]; by = bias[ncol + 1]; }
        float psx = 0.f, psy = 0.f, pqx = 0.f, pqy = 0.f;
        #pragma unroll
        for (int mt = 0; mt < 2; mt++) {
            #pragma unroll
            for (int hh = 0; hh < 2; hh++) {
                int r = rowBase + wm * 32 + mt * 16 + lr + hh * 8;
                if (r < M) {
                    float ox = acc[mt][nt][2 * hh]     + bx;
                    float oy = acc[mt][nt][2 * hh + 1] + by;
                    if (C) {
                        float2 o; o.x = ox; o.y = oy;
                        *(float2*)(C + (size_t)r * NC + gcol) = o;
                    }
                    if (p == 0) {
                        if (dup) {
                            float2 o; o.x = ox; o.y = oy;
                            *(float2*)(dup + (size_t)r * C1 + gcol) = o;
                        }
                    } else if (duph) {
                        __half2 h = __floats2half2_rn(ox, oy);
                        *(__half2*)(duph + (size_t)r * 128 + (gcol - BN)) = h;
                    }
                    if (dostats) {
                        psx += ox; pqx = fmaf(ox, ox, pqx);
                        psy += oy; pqy = fmaf(oy, oy, pqy);
                    }
                }
            }
        }
        if (dostats) {
            atomicAdd(&sSum[ncol],     psx); atomicAdd(&sSq[ncol],     pqx);
            atomicAdd(&sSum[ncol + 1], psy); atomicAdd(&sSq[ncol + 1], pqy);
        }
    }
    if (dostats) {
        __syncthreads();
        if (tid < 64) {
            atomicAdd(&statsOut[tid],      sSum[tid]);
            atomicAdd(&statsOut[C1 + tid], sSq[tid]);
        }
    }
}

// ---------------- host launch ----------------
extern "C" void kernel_launch(void* const* d_in, const int* in_sizes, int n_in,
                              void* d_out, int out_size) {
    const float* x   = (const float*)d_in[0];
    const void*  ei  = d_in[1];
    const float* W1  = (const float*)d_in[2];
    // d_in[3] = B1 (absorbed by BatchNorm)
    const float* g1  = (const float*)d_in[4];
    const float* be1 = (const float*)d_in[5];
    const float* W2  = (const float*)d_in[6];
    // d_in[7] = B2 (absorbed by BatchNorm)
    const float* g2  = (const float*)d_in[8];
    const float* be2 = (const float*)d_in[9];
    const float* Wfc = (const float*)d_in[10];
    const float* bfc = (const float*)d_in[11];
    float* out = (float*)d_out;

    float *Hpre, *H2, *St;
    __half *Zh, *Th;
    int *Cnt;
    cudaGetSymbolAddress((void**)&Zh,   g_Zh);
    cudaGetSymbolAddress((void**)&Th,   g_Th);
    cudaGetSymbolAddress((void**)&Hpre, g_Hpre);
    cudaGetSymbolAddress((void**)&H2,   g_H2);
    cudaGetSymbolAddress((void**)&St,   g_stats);
    cudaGetSymbolAddress((void**)&Cnt,  g_cnt);
    float* StA = St;
    float* StB = St + 2 * C1;

    static cudaStream_t sB = nullptr;
    static cudaEvent_t evFork = nullptr, evJoin = nullptr;
    if (!sB) {
        cudaStreamCreateWithFlags(&sB, cudaStreamNonBlocking);
        cudaEventCreateWithFlags(&evFork, cudaEventDisableTiming);
        cudaEventCreateWithFlags(&evJoin, cudaEventDisableTiming);
    }

    const int TB = 256;
    const int nBlkE  = (EE + TB - 1) / TB;
    const int nBlkSp = (NN + 7) / 8;
    const dim3 gemmG((NN + BM - 1) / BM, 3);
    const dim3 gemmO((NN + BM - 1) / BM, 1);

    // zero both stat buffers once (3 KB) before any producer runs
    cudaMemsetAsync(St, 0, 4 * C1 * sizeof(float));

    // ---- fork: CSR preprocessing on side stream, layer-1 GEMM on main --------
    cudaEventRecord(evFork, 0);
    cudaStreamWaitEvent(sB, evFork, 0);

    k_detect<<<1, 32, 0, sB>>>((const long long*)ei);
    cudaMemsetAsync(Cnt, 0, NN * sizeof(int), sB);
    k_count<<<nBlkE, TB, 0, sB>>>(ei);
    k_bsum<<<SCAN_B, 256, 0, sB>>>();
    k_scan_bsum<<<1, 256, 0, sB>>>();
    k_scan_final<<<SCAN_B, 256, 0, sB>>>();
    k_fill<<<nBlkE, TB, 0, sB>>>(ei);
    cudaEventRecord(evJoin, sB);

    // main stream: layer-1 GEMM (power0 -> Hpre fp32 + stats into StA; Zh fp16)
    tgemm<<<gemmG, TB>>>(x, W1, nullptr, NN, FIN, C1, nullptr,
                         nullptr, nullptr, nullptr, Hpre, Zh, StA);

    cudaStreamWaitEvent(0, evJoin, 0);                // join: SpMM needs CSR + Zh

    // ---- layer 1 propagation (stats fused) ----
    spmm128h<<<nBlkSp, TB>>>(Zh, Hpre, Th, StA);
    spmm64h<<<nBlkSp, TB>>>(Th, Hpre, StA);

    // ---- layer 2 (BN1+ReLU from StA; power0 stats -> StB) ----
    tgemm<<<gemmG, TB>>>(Hpre, W2, nullptr, NN, C1, C1, nullptr,
                         g1, be1, StA, H2, Zh, StB);
    spmm128h<<<nBlkSp, TB>>>(Zh, H2, Th, StB);
    spmm64h<<<nBlkSp, TB>>>(Th, H2, StB);

    // ---- final fc (BN2+ReLU from StB) ----
    tgemm<<<gemmO, TB>>>(H2, Wfc, out, NN, C1, HIDD, bfc,
                         g2, be2, StB, nullptr, nullptr, nullptr);

    (void)in_sizes; (void)n_in; (void)out_size;
}

// round 13
// speedup vs baseline: 1.7716x; 1.0188x over previous
#include <cuda_runtime.h>
#include <cuda_bf16.h>
#include <cuda_fp16.h>
#include <cstdint>

#define NN   50000
#define EE   800000
#define FIN  128
#define HIDD 64
#define C1   192          // P*HID
#define EPSB 1e-5f
#define SCAN_B 196        // ceil(NN/256)

// ---------------- static device scratch (no allocations allowed) ----------------
__device__ __align__(256) __half g_Zh [(size_t)NN * 128];   // fp16 cols 64..191 of layer GEMM out
__device__ __align__(256) __half g_Th [(size_t)NN * HIDD];  // fp16 hop-1 intermediate
__device__ __align__(256) __half g_Hh1[(size_t)NN * C1];    // fp16 layer-1 concat (A of tgemm2)
__device__ __align__(256) __half g_Hh2[(size_t)NN * C1];    // fp16 layer-2 concat (A of tgemm3)
__device__ int   g_cnt[NN];
__device__ int   g_rowptr[NN + 1];
__device__ int   g_pos[NN];
__device__ int   g_bsum[SCAN_B];
__device__ __align__(256) int2  g_edge[EE];        // {col, w as float bits}
__device__ float g_dinv[NN];
// two stat buffers (layer1 / layer2); each: [0..C1) sums, [C1..2C1) sumsq
__device__ __align__(256) float g_stats[2][2 * C1];

// ---------------- per-block dtype sniff (int64 vs int32 edge_index) -------------
// If data is really int32, an int64 view of random index pairs is >= 2^32 a.s.
__device__ __forceinline__ int sniff_is64(const long long* e, int* sFlag) {
    if (threadIdx.x < 32) {
        int bad = 0;
        #pragma unroll
        for (int l = 0; l < 2; l++) {
            long long v = e[threadIdx.x + 32 * l];
            bad |= (v < 0 || v >= NN);
        }
        unsigned m = __ballot_sync(0xffffffffu, bad);
        if (threadIdx.x == 0) *sFlag = (m == 0u);
    }
    __syncthreads();
    return *sFlag;
}

__device__ __forceinline__ int edge_at(const void* p, long long i, int is64) {
    if (is64) return (int)((const long long*)p)[i];
    return ((const int*)p)[i];
}

// ---------------- graph preprocessing ----------------
__global__ void k_count(const void* e) {
    __shared__ int sIs64;
    int is64 = sniff_is64((const long long*)e, &sIs64);
    int i = blockIdx.x * blockDim.x + threadIdx.x;
    if (i < EE) {
        int d = edge_at(e, (long long)EE + i, is64);
        atomicAdd(&g_cnt[d], 1);
    }
}

__global__ void k_bsum() {
    __shared__ int sh[256];
    int i = blockIdx.x * 256 + threadIdx.x;
    sh[threadIdx.x] = (i < NN) ? g_cnt[i] : 0;
    __syncthreads();
    for (int s = 128; s > 0; s >>= 1) {
        if (threadIdx.x < s) sh[threadIdx.x] += sh[threadIdx.x + s];
        __syncthreads();
    }
    if (threadIdx.x == 0) g_bsum[blockIdx.x] = sh[0];
}

// fused: redundant per-block scan of the 196 block sums + local scan + dinv
__global__ void k_scan_final() {
    __shared__ int sb[256];
    __shared__ int sh[256];
    int t = threadIdx.x;
    // inclusive scan of block sums (redundant per block; 196 entries)
    int bv = (t < SCAN_B) ? g_bsum[t] : 0;
    sb[t] = bv;
    __syncthreads();
    for (int off = 1; off < 256; off <<= 1) {
        int tv = (t >= off) ? sb[t - off] : 0;
        __syncthreads();
        sb[t] += tv;
        __syncthreads();
    }
    int blockOff = (blockIdx.x == 0) ? 0 : sb[blockIdx.x - 1];
    // local inclusive scan
    int i = blockIdx.x * 256 + t;
    int v = (i < NN) ? g_cnt[i] : 0;
    sh[t] = v;
    __syncthreads();
    for (int off = 1; off < 256; off <<= 1) {
        int tv = (t >= off) ? sh[t - off] : 0;
        __syncthreads();
        sh[t] += tv;
        __syncthreads();
    }
    int excl = sh[t] - v + blockOff;
    if (i < NN) {
        g_rowptr[i] = excl;
        g_pos[i]    = excl;
        g_dinv[i]   = rsqrtf((float)v + 1.0f);   // +1 self loop
    }
    if (blockIdx.x == 0 && t == 0) g_rowptr[NN] = EE;
}

__global__ void k_fill(const void* e) {
    __shared__ int sIs64;
    int is64 = sniff_is64((const long long*)e, &sIs64);
    int i = blockIdx.x * blockDim.x + threadIdx.x;
    if (i < EE) {
        int s = edge_at(e, i, is64);
        int d = edge_at(e, (long long)EE + i, is64);
        int p = atomicAdd(&g_pos[d], 1);
        int2 ew;
        ew.x = s;
        ew.y = __float_as_int(g_dinv[s] * g_dinv[d]);
        g_edge[p] = ew;
    }
}

// ------- hop 1: gather fp16 Zh rows; power-1 -> H fp16 (+stats), A*z2 -> Th ----
// grid is exact: 6250 blocks x 8 warps = NN rows.
__global__ __launch_bounds__(256) void spmm128h(
    const __half* __restrict__ Zh, __half* __restrict__ H, __half* __restrict__ Th,
    float* __restrict__ stats)
{
    __shared__ float sS[64], sQ[64];
    if (threadIdx.x < 64) { sS[threadIdx.x] = 0.f; sQ[threadIdx.x] = 0.f; }
    __syncthreads();

    int warp = (blockIdx.x * blockDim.x + threadIdx.x) >> 5;
    int lane = threadIdx.x & 31;
    float dv = g_dinv[warp];
    float ws = dv * dv;
    uint2 zp = ((const uint2*)(Zh + (size_t)warp * 128))[lane];     // 4 halves
    float2 z0 = __half22float2(*(const __half2*)&zp.x);
    float2 z1 = __half22float2(*(const __half2*)&zp.y);
    float a0 = ws * z0.x, a1 = ws * z0.y, a2 = ws * z1.x, a3 = ws * z1.y;
    int e0 = g_rowptr[warp], e1 = g_rowptr[warp + 1];
    #pragma unroll 4
    for (int e = e0; e < e1; e++) {
        int2 ew  = __ldg(&g_edge[e]);
        int c    = ew.x;
        float wt = __int_as_float(ew.y);
        uint2 vp = ((const uint2*)(Zh + (size_t)c * 128))[lane];
        float2 v0 = __half22float2(*(const __half2*)&vp.x);
        float2 v1 = __half22float2(*(const __half2*)&vp.y);
        a0 = fmaf(wt, v0.x, a0);
        a1 = fmaf(wt, v0.y, a1);
        a2 = fmaf(wt, v1.x, a2);
        a3 = fmaf(wt, v1.y, a3);
    }
    uint2 op;
    *(__half2*)&op.x = __floats2half2_rn(a0, a1);
    *(__half2*)&op.y = __floats2half2_rn(a2, a3);
    if (lane < 16) {
        *(uint2*)(H + (size_t)warp * C1 + HIDD + lane * 4) = op;
        int b = lane * 4;
        atomicAdd(&sS[b + 0], a0); atomicAdd(&sQ[b + 0], a0 * a0);
        atomicAdd(&sS[b + 1], a1); atomicAdd(&sQ[b + 1], a1 * a1);
        atomicAdd(&sS[b + 2], a2); atomicAdd(&sQ[b + 2], a2 * a2);
        atomicAdd(&sS[b + 3], a3); atomicAdd(&sQ[b + 3], a3 * a3);
    } else {
        *(uint2*)(Th + (size_t)warp * HIDD + (lane - 16) * 4) = op;
    }
    __syncthreads();
    if (threadIdx.x < 64) {
        atomicAdd(&stats[HIDD + threadIdx.x], sS[threadIdx.x]);
        atomicAdd(&stats[C1 + HIDD + threadIdx.x], sQ[threadIdx.x]);
    }
}

// ------- hop 2: gather fp16 Th rows; power-2 -> H fp16 (+stats) -----------------
__global__ __launch_bounds__(256) void spmm64h(
    const __half* __restrict__ Th, __half* __restrict__ H, float* __restrict__ stats)
{
    __shared__ float sS[64], sQ[64];
    if (threadIdx.x < 64) { sS[threadIdx.x] = 0.f; sQ[threadIdx.x] = 0.f; }
    __syncthreads();

    int warp = (blockIdx.x * blockDim.x + threadIdx.x) >> 5;
    int lane = threadIdx.x & 31;
    float dv = g_dinv[warp];
    float ws = dv * dv;
    uint32_t zp = ((const uint32_t*)(Th + (size_t)warp * HIDD))[lane];
    float2 z = __half22float2(*(const __half2*)&zp);
    float ax = ws * z.x, ay = ws * z.y;
    int e0 = g_rowptr[warp], e1 = g_rowptr[warp + 1];
    #pragma unroll 4
    for (int e = e0; e < e1; e++) {
        int2 ew  = __ldg(&g_edge[e]);
        int c    = ew.x;
        float wt = __int_as_float(ew.y);
        uint32_t vp = ((const uint32_t*)(Th + (size_t)c * HIDD))[lane];
        float2 v = __half22float2(*(const __half2*)&vp);
        ax = fmaf(wt, v.x, ax);
        ay = fmaf(wt, v.y, ay);
    }
    *(__half2*)(H + (size_t)warp * C1 + 2 * HIDD + lane * 2) = __floats2half2_rn(ax, ay);
    int b = lane * 2;
    atomicAdd(&sS[b + 0], ax); atomicAdd(&sQ[b + 0], ax * ax);
    atomicAdd(&sS[b + 1], ay); atomicAdd(&sQ[b + 1], ay * ay);
    __syncthreads();
    if (threadIdx.x < 64) {
        atomicAdd(&stats[2 * HIDD + threadIdx.x], sS[threadIdx.x]);
        atomicAdd(&stats[C1 + 2 * HIDD + threadIdx.x], sQ[threadIdx.x]);
    }
}

// ------------- bf16 split-2 tensor-core GEMM (m16n8k16, 3-term compensation) ----
// A is fp32 (AHALF=false) or fp16 (AHALF=true). BN+ReLU on A from statsIn if gvec.
// p==0: fp16 store into hout (ld C1, col gcol) + power-0 stats into statsOut.
// p>=1: fp16 store into zh (ld 128, col gcol-64). C fp32 (ld NC) if non-null.
#define BM 128
#define BN 64
#define BK 32
#define KP 16
#define AST 20
#define BST 72

__device__ __forceinline__ uint32_t pack_bf16(float x, float y) {
    __nv_bfloat162 t;
    t.x = __float2bfloat16_rn(x);
    t.y = __float2bfloat16_rn(y);
    return *reinterpret_cast<uint32_t*>(&t);
}
__device__ __forceinline__ float bf_hi_f(float x) {
    return __bfloat162float(__float2bfloat16_rn(x));
}

__device__ __forceinline__ void mma_bf16(float* d, const uint32_t* a, const uint32_t* b) {
    asm volatile(
        "mma.sync.aligned.m16n8k16.row.col.f32.bf16.bf16.f32 "
        "{%0,%1,%2,%3},{%4,%5,%6,%7},{%8,%9},{%0,%1,%2,%3};\n"
        : "+f"(d[0]), "+f"(d[1]), "+f"(d[2]), "+f"(d[3])
        : "r"(a[0]), "r"(a[1]), "r"(a[2]), "r"(a[3]), "r"(b[0]), "r"(b[1]));
}

template<bool AHALF>
__global__ __launch_bounds__(256, 2) void tgemm(
    const void* __restrict__ Avoid, const float* __restrict__ Bmat,
    float* __restrict__ C, int M, int K, int NC,
    const float* __restrict__ bias,
    const float* __restrict__ gvec, const float* __restrict__ bevec,
    const float* __restrict__ statsIn,
    __half* __restrict__ hout, __half* __restrict__ zh,
    float* __restrict__ statsOut)
{
    __shared__ uint32_t AsH[BM * AST];
    __shared__ uint32_t AsL[BM * AST];
    __shared__ uint32_t BsH[KP * BST];
    __shared__ uint32_t BsL[KP * BST];
    __shared__ float sSc[C1];
    __shared__ float sSh[C1];
    __shared__ float sSum[64];
    __shared__ float sSq[64];
    const float*  Af = (const float*)Avoid;
    const __half* Ah = (const __half*)Avoid;
    int p = blockIdx.y;
    const float* Bp = Bmat + (size_t)p * K * BN;
    int rowBase = blockIdx.x * BM;
    int tid  = threadIdx.x;
    int lane = tid & 31;
    int w    = tid >> 5;
    int wm   = w & 3;
    int wn   = w >> 2;
    int lr   = lane >> 2;
    int lc   = lane & 3;

    bool hasbn = (gvec != nullptr);
    bool dostats = (statsOut != nullptr) && (p == 0);
    if (tid < 64) { sSum[tid] = 0.f; sSq[tid] = 0.f; }
    if (hasbn && tid < C1) {
        float mu  = statsIn[tid] * (1.0f / NN);
        float var = statsIn[C1 + tid] * (1.0f / NN) - mu * mu;
        float inv = rsqrtf(var + EPSB);
        float sc  = inv * gvec[tid];
        sSc[tid] = sc;
        sSh[tid] = bevec[tid] - mu * sc;
    }
    __syncthreads();

    const int ar  = tid >> 3;
    const int ac4 = tid & 7;
    const int bkp = tid >> 4;
    const int bn4 = tid & 15;

    float acc[2][4][4];
    #pragma unroll
    for (int mt = 0; mt < 2; mt++)
        #pragma unroll
        for (int nt = 0; nt < 4; nt++)
            #pragma unroll
            for (int i = 0; i < 4; i++) acc[mt][nt][i] = 0.f;

    // raw prefetch registers (converted during the pack phase)
    float4 avF[4];
    uint2  avH[4];
    float4 avB0, avB1;
    #pragma unroll
    for (int l = 0; l < 4; l++) {
        int grow = rowBase + ar + l * 32;
        if (AHALF) {
            avH[l] = (grow < M) ? *(const uint2*)(Ah + (size_t)grow * K + ac4 * 4)
                                : make_uint2(0u, 0u);
        } else {
            avF[l] = (grow < M) ? *(const float4*)(Af + (size_t)grow * K + ac4 * 4)
                                : make_float4(0.f, 0.f, 0.f, 0.f);
        }
    }
    {
        const float* r0p = Bp + (size_t)(2 * bkp) * BN + bn4 * 4;
        avB0 = *(const float4*)r0p;
        avB1 = *(const float4*)(r0p + BN);
    }

    for (int k0 = 0; k0 < K; k0 += BK) {
        #pragma unroll
        for (int l = 0; l < 4; l++) {
            float4 v;
            if (AHALF) {
                float2 p0 = __half22float2(*(const __half2*)&avH[l].x);
                float2 p1 = __half22float2(*(const __half2*)&avH[l].y);
                v = make_float4(p0.x, p0.y, p1.x, p1.y);
            } else {
                v = avF[l];
            }
            if (hasbn) {
                int kc = k0 + ac4 * 4;
                v.x = fmaxf(0.f, fmaf(v.x, sSc[kc + 0], sSh[kc + 0]));
                v.y = fmaxf(0.f, fmaf(v.y, sSc[kc + 1], sSh[kc + 1]));
                v.z = fmaxf(0.f, fmaf(v.z, sSc[kc + 2], sSh[kc + 2]));
                v.w = fmaxf(0.f, fmaf(v.w, sSc[kc + 3], sSh[kc + 3]));
            }
            int row = ar + l * 32;
            int kp  = ac4 * 2;
            AsH[row * AST + kp]     = pack_bf16(v.x, v.y);
            AsH[row * AST + kp + 1] = pack_bf16(v.z, v.w);
            AsL[row * AST + kp]     = pack_bf16(v.x - bf_hi_f(v.x), v.y - bf_hi_f(v.y));
            AsL[row * AST + kp + 1] = pack_bf16(v.z - bf_hi_f(v.z), v.w - bf_hi_f(v.w));
        }
        {
            float4 u0 = avB0, u1 = avB1;
            uint32_t* dh = &BsH[bkp * BST + bn4 * 4];
            uint32_t* dl = &BsL[bkp * BST + bn4 * 4];
            dh[0] = pack_bf16(u0.x, u1.x);
            dh[1] = pack_bf16(u0.y, u1.y);
            dh[2] = pack_bf16(u0.z, u1.z);
            dh[3] = pack_bf16(u0.w, u1.w);
            dl[0] = pack_bf16(u0.x - bf_hi_f(u0.x), u1.x - bf_hi_f(u1.x));
            dl[1] = pack_bf16(u0.y - bf_hi_f(u0.y), u1.y - bf_hi_f(u1.y));
            dl[2] = pack_bf16(u0.z - bf_hi_f(u0.z), u1.z - bf_hi_f(u1.z));
            dl[3] = pack_bf16(u0.w - bf_hi_f(u0.w), u1.w - bf_hi_f(u1.w));
        }
        __syncthreads();

        int kn = k0 + BK;
        if (kn < K) {
            #pragma unroll
            for (int l = 0; l < 4; l++) {
                int grow = rowBase + ar + l * 32;
                if (AHALF) {
                    avH[l] = (grow < M) ? *(const uint2*)(Ah + (size_t)grow * K + kn + ac4 * 4)
                                        : make_uint2(0u, 0u);
                } else {
                    avF[l] = (grow < M) ? *(const float4*)(Af + (size_t)grow * K + kn + ac4 * 4)
                                        : make_float4(0.f, 0.f, 0.f, 0.f);
                }
            }
            const float* r0p = Bp + (size_t)(kn + 2 * bkp) * BN + bn4 * 4;
            avB0 = *(const float4*)r0p;
            avB1 = *(const float4*)(r0p + BN);
        }

        #pragma unroll
        for (int c = 0; c < 2; c++) {
            int kpb = c * 8;
            uint32_t ahi[2][4], alo[2][4];
            #pragma unroll
            for (int mt = 0; mt < 2; mt++) {
                int r0 = wm * 32 + mt * 16 + lr;
                ahi[mt][0] = AsH[r0 * AST + kpb + lc];
                ahi[mt][1] = AsH[(r0 + 8) * AST + kpb + lc];
                ahi[mt][2] = AsH[r0 * AST + kpb + lc + 4];
                ahi[mt][3] = AsH[(r0 + 8) * AST + kpb + lc + 4];
                alo[mt][0] = AsL[r0 * AST + kpb + lc];
                alo[mt][1] = AsL[(r0 + 8) * AST + kpb + lc];
                alo[mt][2] = AsL[r0 * AST + kpb + lc + 4];
                alo[mt][3] = AsL[(r0 + 8) * AST + kpb + lc + 4];
            }
            uint32_t bhi[4][2], blo[4][2];
            #pragma unroll
            for (int nt = 0; nt < 4; nt++) {
                int n0 = wn * 32 + nt * 8 + lr;
                bhi[nt][0] = BsH[(kpb + lc) * BST + n0];
                bhi[nt][1] = BsH[(kpb + lc + 4) * BST + n0];
                blo[nt][0] = BsL[(kpb + lc) * BST + n0];
                blo[nt][1] = BsL[(kpb + lc + 4) * BST + n0];
            }
            #pragma unroll
            for (int mt = 0; mt < 2; mt++)
                #pragma unroll
                for (int nt = 0; nt < 4; nt++) {
                    mma_bf16(acc[mt][nt], ahi[mt], bhi[nt]);
                    mma_bf16(acc[mt][nt], ahi[mt], blo[nt]);
                    mma_bf16(acc[mt][nt], alo[mt], bhi[nt]);
                }
        }
        __syncthreads();
    }

    #pragma unroll
    for (int nt = 0; nt < 4; nt++) {
        int ncol = wn * 32 + nt * 8 + lc * 2;
        int gcol = p * BN + ncol;
        float bx = 0.f, by = 0.f;
        if (bias) { bx = bias[ncol]; by = bias[ncol + 1]; }
        float psx = 0.f, psy = 0.f, pqx = 0.f, pqy = 0.f;
        #pragma unroll
        for (int mt = 0; mt < 2; mt++) {
            #pragma unroll
            for (int hh = 0; hh < 2; hh++) {
                int r = rowBase + wm * 32 + mt * 16 + lr + hh * 8;
                if (r < M) {
                    float ox = acc[mt][nt][2 * hh]     + bx;
                    float oy = acc[mt][nt][2 * hh + 1] + by;
                    if (C) {
                        float2 o; o.x = ox; o.y = oy;
                        *(float2*)(C + (size_t)r * NC + gcol) = o;
                    }
                    if (p == 0) {
                        if (hout)
                            *(__half2*)(hout + (size_t)r * C1 + gcol) = __floats2half2_rn(ox, oy);
                    } else if (zh) {
                        *(__half2*)(zh + (size_t)r * 128 + (gcol - BN)) = __floats2half2_rn(ox, oy);
                    }
                    if (dostats) {
                        psx += ox; pqx = fmaf(ox, ox, pqx);
                        psy += oy; pqy = fmaf(oy, oy, pqy);
                    }
                }
            }
        }
        if (dostats) {
            atomicAdd(&sSum[ncol],     psx); atomicAdd(&sSq[ncol],     pqx);
            atomicAdd(&sSum[ncol + 1], psy); atomicAdd(&sSq[ncol + 1], pqy);
        }
    }
    if (dostats) {
        __syncthreads();
        if (tid < 64) {
            atomicAdd(&statsOut[tid],      sSum[tid]);
            atomicAdd(&statsOut[C1 + tid], sSq[tid]);
        }
    }
}

// ---------------- host launch ----------------
extern "C" void kernel_launch(void* const* d_in, const int* in_sizes, int n_in,
                              void* d_out, int out_size) {
    const float* x   = (const float*)d_in[0];
    const void*  ei  = d_in[1];
    const float* W1  = (const float*)d_in[2];
    // d_in[3] = B1 (absorbed by BatchNorm)
    const float* g1  = (const float*)d_in[4];
    const float* be1 = (const float*)d_in[5];
    const float* W2  = (const float*)d_in[6];
    // d_in[7] = B2 (absorbed by BatchNorm)
    const float* g2  = (const float*)d_in[8];
    const float* be2 = (const float*)d_in[9];
    const float* Wfc = (const float*)d_in[10];
    const float* bfc = (const float*)d_in[11];
    float* out = (float*)d_out;

    float *St;
    __half *Zh, *Th, *Hh1, *Hh2;
    int *Cnt;
    cudaGetSymbolAddress((void**)&Zh,  g_Zh);
    cudaGetSymbolAddress((void**)&Th,  g_Th);
    cudaGetSymbolAddress((void**)&Hh1, g_Hh1);
    cudaGetSymbolAddress((void**)&Hh2, g_Hh2);
    cudaGetSymbolAddress((void**)&St,  g_stats);
    cudaGetSymbolAddress((void**)&Cnt, g_cnt);
    float* StA = St;
    float* StB = St + 2 * C1;

    static cudaStream_t sB = nullptr;
    static cudaEvent_t evFork = nullptr, evJoin = nullptr;
    if (!sB) {
        cudaStreamCreateWithFlags(&sB, cudaStreamNonBlocking);
        cudaEventCreateWithFlags(&evFork, cudaEventDisableTiming);
        cudaEventCreateWithFlags(&evJoin, cudaEventDisableTiming);
    }

    const int TB = 256;
    const int nBlkE  = (EE + TB - 1) / TB;
    const int nBlkSp = (NN + 7) / 8;
    const dim3 gemmG((NN + BM - 1) / BM, 3);
    const dim3 gemmO((NN + BM - 1) / BM, 1);

    // zero both stat buffers once (3 KB) before any producer runs
    cudaMemsetAsync(St, 0, 4 * C1 * sizeof(float));

    // ---- fork: CSR preprocessing on side stream, layer-1 GEMM on main --------
    cudaEventRecord(evFork, 0);
    cudaStreamWaitEvent(sB, evFork, 0);

    cudaMemsetAsync(Cnt, 0, NN * sizeof(int), sB);
    k_count<<<nBlkE, TB, 0, sB>>>(ei);
    k_bsum<<<SCAN_B, 256, 0, sB>>>();
    k_scan_final<<<SCAN_B, 256, 0, sB>>>();
    k_fill<<<nBlkE, TB, 0, sB>>>(ei);
    cudaEventRecord(evJoin, sB);

    // main stream: layer-1 GEMM (power0 -> Hh1 fp16 + stats into StA; Zh fp16)
    tgemm<false><<<gemmG, TB>>>(x, W1, nullptr, NN, FIN, C1, nullptr,
                                nullptr, nullptr, nullptr, Hh1, Zh, StA);

    cudaStreamWaitEvent(0, evJoin, 0);                // join: SpMM needs CSR + Zh

    // ---- layer 1 propagation (stats fused) ----
    spmm128h<<<nBlkSp, TB>>>(Zh, Hh1, Th, StA);
    spmm64h<<<nBlkSp, TB>>>(Th, Hh1, StA);

    // ---- layer 2 (BN1+ReLU from StA; power0 stats -> StB) ----
    tgemm<true><<<gemmG, TB>>>(Hh1, W2, nullptr, NN, C1, C1, nullptr,
                               g1, be1, StA, Hh2, Zh, StB);
    spmm128h<<<nBlkSp, TB>>>(Zh, Hh2, Th, StB);
    spmm64h<<<nBlkSp, TB>>>(Th, Hh2, StB);

    // ---- final fc (BN2+ReLU from StB) ----
    tgemm<true><<<gemmO, TB>>>(Hh2, Wfc, out, NN, C1, HIDD, bfc,
                               g2, be2, StB, nullptr, nullptr, nullptr);

    (void)in_sizes; (void)n_in; (void)out_size;
}